// round 1
// baseline (speedup 1.0000x reference)
#include <cuda_runtime.h>
#include <math.h>
#include <stdint.h>

// Problem constants (fixed shapes)
#define BB   2
#define NN   512
#define DIMV 384
#define HH   8
#define TOK  (BB*NN)          // 1024

#define SCALAR_SCALE 0.14433756729740643f   // (3*16)^-0.5
#define POINT_SCALE  0.13608276348795434f   // (3*4*4.5)^-0.5
#define PAIR_SCALE   0.57735026918962576f   // 3^-0.5
#define EPSV 1e-8f

// ---------------- device scratch (no allocations allowed) ----------------
__device__ float g_qs[TOK*128];
__device__ float g_ks[TOK*128];
__device__ float g_vs[TOK*128];
__device__ float g_qp[TOK*96];
__device__ float g_kp[TOK*96];
__device__ float g_vp[TOK*96];
__device__ float g_qsq[TOK*8];
__device__ float g_ksq[TOK*8];
__device__ float g_feats[TOK*1280];

// ---------------- generic tiled SGEMM: C = A(MxK) @ W(KxN) (+bias) --------
// M % 64 == 0, N % 32 == 0, K % 32 == 0. block (32,8), grid (N/32, M/64).
__global__ __launch_bounds__(256) void sgemm_kernel(
    const float* __restrict__ A, const float* __restrict__ W,
    const float* __restrict__ bias, float* __restrict__ C,
    int M, int N, int K)
{
    __shared__ float As[64*32];
    __shared__ float Ws[32*32];
    const int tx  = threadIdx.x;         // 0..31
    const int ty  = threadIdx.y;         // 0..7
    const int tid = ty*32 + tx;
    const int row0 = blockIdx.y*64;
    const int col0 = blockIdx.x*32;

    float acc[8];
#pragma unroll
    for (int i = 0; i < 8; ++i) acc[i] = 0.f;

    for (int k0 = 0; k0 < K; k0 += 32) {
#pragma unroll
        for (int l = 0; l < 8; ++l) {
            int e = l*256 + tid;
            int ar = e >> 5, ak = e & 31;
            As[e] = A[(size_t)(row0+ar)*K + k0 + ak];
        }
#pragma unroll
        for (int l = 0; l < 4; ++l) {
            int e = l*256 + tid;
            int wr = e >> 5, wc = e & 31;
            Ws[e] = W[(size_t)(k0+wr)*N + col0 + wc];
        }
        __syncthreads();
#pragma unroll
        for (int kk = 0; kk < 32; ++kk) {
            float wv = Ws[kk*32 + tx];
#pragma unroll
            for (int i = 0; i < 8; ++i)
                acc[i] += As[(ty*8 + i)*32 + kk] * wv;
        }
        __syncthreads();
    }
    float bv = bias ? bias[col0 + tx] : 0.f;
#pragma unroll
    for (int i = 0; i < 8; ++i)
        C[(size_t)(row0 + ty*8 + i)*N + col0 + tx] = acc[i] + bv;
}

// ---------------- rotate + translate qp/kp/vp in place, compute sq norms --
// grid TOK, 32 threads. Thread t handles (h,d) pair t (h=t/4, d=t%4).
__global__ void rotate_kernel(const float* __restrict__ rot,
                              const float* __restrict__ trans)
{
    const int bn  = blockIdx.x;
    const int tid = threadIdx.x;   // 0..31

    float r[9], t3[3];
#pragma unroll
    for (int k = 0; k < 9; ++k) r[k] = rot[bn*9 + k];
#pragma unroll
    for (int k = 0; k < 3; ++k) t3[k] = trans[bn*3 + k];

    float* arrs[3] = { g_qp, g_kp, g_vp };
    float sq0 = 0.f, sq1 = 0.f;
#pragma unroll
    for (int a = 0; a < 3; ++a) {
        float* base = arrs[a] + (size_t)bn*96 + tid*3;
        float c0 = base[0], c1 = base[1], c2 = base[2];
        // out[r] = sum_c in[c] * R[c*3+r] + t[r]
        float o0 = c0*r[0] + c1*r[3] + c2*r[6] + t3[0];
        float o1 = c0*r[1] + c1*r[4] + c2*r[7] + t3[1];
        float o2 = c0*r[2] + c1*r[5] + c2*r[8] + t3[2];
        base[0] = o0; base[1] = o1; base[2] = o2;
        float s = o0*o0 + o1*o1 + o2*o2;
        if (a == 0) sq0 = s;
        if (a == 1) sq1 = s;
    }
    // reduce over d within quads (h = tid/4)
#pragma unroll
    for (int off = 1; off < 4; off <<= 1) {
        sq0 += __shfl_xor_sync(0xffffffffu, sq0, off);
        sq1 += __shfl_xor_sync(0xffffffffu, sq1, off);
    }
    if ((tid & 3) == 0) {
        g_qsq[bn*8 + (tid >> 2)] = sq0;
        g_ksq[bn*8 + (tid >> 2)] = sq1;
    }
}

// ---------------- fused single-pass attention (online softmax) -----------
// grid = TOK (one block per (b,i)), 256 threads.
__global__ __launch_bounds__(256) void ipa_attn_kernel(
    const float* __restrict__ pairwise,
    const float* __restrict__ rot,
    const float* __restrict__ trans,
    const float* __restrict__ w_pair,
    const float* __restrict__ b_pair,
    const float* __restrict__ point_w)
{
    __shared__ float pairT[64*129];      // padded rows: bank-conflict-free
    __shared__ float wexp[8*64];
    __shared__ float qs_s[128];
    __shared__ float qp_s[96];
    __shared__ float qsq_s[8];
    __shared__ float wpair_s[128*8];
    __shared__ float m_s[8], l_s[8], alpha_s[8], coef_s[8], bp_s[8];
    __shared__ float R_s[9], T_s[3];
    __shared__ float pts_s[96], ptsl_s[96];

    const int tid = threadIdx.x;
    const int bn  = blockIdx.x;
    const int b   = bn >> 9;
    // (i implicit in bn)

    if (tid < 128) qs_s[tid] = g_qs[(size_t)bn*128 + tid];
    if (tid < 96)  qp_s[tid] = g_qp[(size_t)bn*96 + tid];
    if (tid < 8) {
        qsq_s[tid] = g_qsq[bn*8 + tid];
        m_s[tid]   = -1e30f;
        l_s[tid]   = 0.f;
        bp_s[tid]  = b_pair[tid];
        float x = point_w[tid];
        coef_s[tid] = -0.5f * POINT_SCALE * log1pf(__expf(x));   // softplus
    }
#pragma unroll
    for (int l = 0; l < 4; ++l) wpair_s[l*256 + tid] = w_pair[l*256 + tid];
    if (tid < 9) R_s[tid] = rot[bn*9 + tid];
    if (tid < 3) T_s[tid] = trans[bn*3 + tid];
    __syncthreads();

    // accumulator ownership
    const int h_p  = tid >> 5;           // pair-acc head
    const int lane = tid & 31;
    float accp0 = 0.f, accp1 = 0.f, accp2 = 0.f, accp3 = 0.f;

    const bool has_v = tid < 224;        // 8 heads x 28 value-features
    int h_v = 0, f_v = 0;
    if (has_v) { h_v = tid / 28; f_v = tid - h_v*28; }
    float accv = 0.f;

    const int jj_l = tid >> 2;           // 0..63 for logit phase
    const int hb_l = tid & 3;

    const float* gp_base = pairwise + (size_t)bn * NN * 128;

    for (int tile = 0; tile < 8; ++tile) {
        const int j0 = tile * 64;
        // ---- load pairwise tile (64 x 128) into padded smem ----
        const float* gp = gp_base + (size_t)j0 * 128;
#pragma unroll
        for (int l = 0; l < 32; ++l) {
            int e  = l*256 + tid;
            int jj = e >> 7, p = e & 127;
            pairT[jj*129 + p] = gp[e];
        }
        __syncthreads();

        // ---- logits: thread handles (jj, hb) and (jj, hb+4) ----
        {
            const int j = j0 + jj_l;
            const size_t bj = (size_t)b*NN + j;
            const float* pr = &pairT[jj_l*129];
#pragma unroll
            for (int hh = 0; hh < 2; ++hh) {
                const int h = hb_l + hh*4;
                const float* ksr = g_ks + bj*128 + h*16;
                const float* qsr = qs_s + h*16;
                float s = 0.f;
#pragma unroll
                for (int f = 0; f < 16; ++f) s += qsr[f]*ksr[f];
                const float* kpr = g_kp + bj*96 + h*12;
                const float* qpr = qp_s + h*12;
                float dt = 0.f;
#pragma unroll
                for (int e = 0; e < 12; ++e) dt += qpr[e]*kpr[e];
                float dist = qsq_s[h] + g_ksq[bj*8 + h] - 2.f*dt;
                float bias = bp_s[h];
#pragma unroll 16
                for (int p = 0; p < 128; ++p) bias += pr[p]*wpair_s[p*8 + h];
                wexp[h*64 + jj_l] = s*SCALAR_SCALE + bias*PAIR_SCALE + coef_s[h]*dist;
            }
        }
        __syncthreads();

        // ---- online softmax update (warp w owns head w) ----
        {
            const int w = tid >> 5;
            float v0 = wexp[w*64 + lane], v1 = wexp[w*64 + 32 + lane];
            float mx = fmaxf(v0, v1);
#pragma unroll
            for (int off = 16; off; off >>= 1)
                mx = fmaxf(mx, __shfl_xor_sync(0xffffffffu, mx, off));
            float mold = m_s[w];
            float mnew = fmaxf(mold, mx);
            float a  = __expf(mold - mnew);
            float e0 = __expf(v0 - mnew), e1 = __expf(v1 - mnew);
            wexp[w*64 + lane]      = e0;
            wexp[w*64 + 32 + lane] = e1;
            float sm = e0 + e1;
#pragma unroll
            for (int off = 16; off; off >>= 1)
                sm += __shfl_xor_sync(0xffffffffu, sm, off);
            if (lane == 0) { l_s[w] = l_s[w]*a + sm; m_s[w] = mnew; alpha_s[w] = a; }
        }
        __syncthreads();

        // ---- accumulate res_pair (all 256 threads: head h_p, p = lane+32k) ----
        {
            float a = alpha_s[h_p];
            accp0 *= a; accp1 *= a; accp2 *= a; accp3 *= a;
            const float* we = &wexp[h_p*64];
#pragma unroll 4
            for (int jj = 0; jj < 64; ++jj) {
                float wv = we[jj];
                const float* row = &pairT[jj*129 + lane];
                accp0 += wv*row[0];
                accp1 += wv*row[32];
                accp2 += wv*row[64];
                accp3 += wv*row[96];
            }
        }
        // ---- accumulate res_scalar / res_pts (threads 0..223) ----
        if (has_v) {
            float a = alpha_s[h_v];
            accv *= a;
            const float* we = &wexp[h_v*64];
            const size_t base = (size_t)b*NN + j0;
            const float* src;
            int stride;
            if (f_v < 16) { src = g_vs + base*128 + h_v*16 + f_v;      stride = 128; }
            else          { src = g_vp + base*96  + h_v*12 + (f_v-16); stride = 96;  }
#pragma unroll 8
            for (int jj = 0; jj < 64; ++jj) accv += we[jj]*src[(size_t)jj*stride];
        }
        __syncthreads();
    }

    // ---- finalize ----
    float* fr = g_feats + (size_t)bn*1280;
    {
        float il = 1.0f / l_s[h_p];
        fr[256 + h_p*128 + lane]      = accp0*il;
        fr[256 + h_p*128 + lane + 32] = accp1*il;
        fr[256 + h_p*128 + lane + 64] = accp2*il;
        fr[256 + h_p*128 + lane + 96] = accp3*il;
    }
    if (has_v) {
        float il = 1.0f / l_s[h_v];
        float r = accv*il;
        if (f_v < 16) fr[h_v*16 + f_v] = r;              // res_scalar
        else          pts_s[h_v*12 + (f_v-16)] = r;      // global-frame pts
    }
    __syncthreads();
    if (tid < 96) {  // local-frame points: out[r] = sum_c (v[c]-t[c]) * R[r*3+c]
        int hd = tid / 3, r = tid - hd*3;
        float c0 = pts_s[hd*3 + 0] - T_s[0];
        float c1 = pts_s[hd*3 + 1] - T_s[1];
        float c2 = pts_s[hd*3 + 2] - T_s[2];
        float loc = c0*R_s[r*3 + 0] + c1*R_s[r*3 + 1] + c2*R_s[r*3 + 2];
        fr[128 + tid] = loc;
        ptsl_s[tid]   = loc;
    }
    __syncthreads();
    if (tid < 32) {
        float x = ptsl_s[tid*3], y = ptsl_s[tid*3 + 1], z = ptsl_s[tid*3 + 2];
        fr[224 + tid] = sqrtf(x*x + y*y + z*z + EPSV);
    }
}

// ---------------- launcher ----------------
extern "C" void kernel_launch(void* const* d_in, const int* in_sizes, int n_in,
                              void* d_out, int out_size)
{
    const float* q_single  = (const float*)d_in[0];
    const float* kv_single = (const float*)d_in[1];
    const float* pairwise  = (const float*)d_in[2];
    const float* rot       = (const float*)d_in[3];
    const float* trans     = (const float*)d_in[4];
    // d_in[5], d_in[6]: q_mask / kv_mask (all true) - unused
    const float* w_sq   = (const float*)d_in[7];
    const float* w_sk   = (const float*)d_in[8];
    const float* w_sv   = (const float*)d_in[9];
    const float* w_pq   = (const float*)d_in[10];
    const float* w_pk   = (const float*)d_in[11];
    const float* w_pv   = (const float*)d_in[12];
    const float* w_pair = (const float*)d_in[13];
    const float* b_pair = (const float*)d_in[14];
    const float* pw     = (const float*)d_in[15];
    const float* w_out  = (const float*)d_in[16];
    const float* b_out  = (const float*)d_in[17];
    float* out = (float*)d_out;

    float *p_qs, *p_ks, *p_vs, *p_qp, *p_kp, *p_vp, *p_feats;
    cudaGetSymbolAddress((void**)&p_qs, g_qs);
    cudaGetSymbolAddress((void**)&p_ks, g_ks);
    cudaGetSymbolAddress((void**)&p_vs, g_vs);
    cudaGetSymbolAddress((void**)&p_qp, g_qp);
    cudaGetSymbolAddress((void**)&p_kp, g_kp);
    cudaGetSymbolAddress((void**)&p_vp, g_vp);
    cudaGetSymbolAddress((void**)&p_feats, g_feats);

    dim3 blk(32, 8);
    // projections: M=1024, K=384
    sgemm_kernel<<<dim3(4, 16), blk>>>(q_single,  w_sq, nullptr, p_qs, TOK, 128, DIMV);
    sgemm_kernel<<<dim3(4, 16), blk>>>(kv_single, w_sk, nullptr, p_ks, TOK, 128, DIMV);
    sgemm_kernel<<<dim3(4, 16), blk>>>(kv_single, w_sv, nullptr, p_vs, TOK, 128, DIMV);
    sgemm_kernel<<<dim3(3, 16), blk>>>(q_single,  w_pq, nullptr, p_qp, TOK,  96, DIMV);
    sgemm_kernel<<<dim3(3, 16), blk>>>(kv_single, w_pk, nullptr, p_kp, TOK,  96, DIMV);
    sgemm_kernel<<<dim3(3, 16), blk>>>(kv_single, w_pv, nullptr, p_vp, TOK,  96, DIMV);

    rotate_kernel<<<TOK, 32>>>(rot, trans);

    ipa_attn_kernel<<<TOK, 256>>>(pairwise, rot, trans, w_pair, b_pair, pw);

    // output projection: feats(1024x1280) @ w_out(1280x384) + b_out
    sgemm_kernel<<<dim3(12, 16), blk>>>(p_feats, w_out, b_out, out, TOK, DIMV, 1280);
}

// round 2
// speedup vs baseline: 1.1649x; 1.1649x over previous
#include <cuda_runtime.h>
#include <math.h>
#include <stdint.h>

// Problem constants (fixed shapes)
#define BB   2
#define NN   512
#define DIMV 384
#define HH   8
#define TOK  (BB*NN)          // 1024

#define SCALAR_SCALE 0.14433756729740643f   // (3*16)^-0.5
#define POINT_SCALE  0.13608276348795434f   // (3*4*4.5)^-0.5
#define PAIR_SCALE   0.57735026918962576f   // 3^-0.5
#define EPSV 1e-8f

// ---------------- device scratch ----------------
// g_q  row layout (stride 224): qs[0:128), qp[128:224)
// g_kv row layout (stride 448): ks[0:128), vs[128:256), kp[256:352), vp[352:448)
__device__ float g_q[TOK*224];
__device__ float g_kv[TOK*448];
__device__ float g_qsq[TOK*8];
__device__ float g_ksq[TOK*8];
__device__ float g_feats[TOK*1280];

// =====================================================================
// Fused projection GEMM: all 6 projections in one launch.
// Tile: 64(M) x 32(N), K-step 16, 256 threads, each thread 4x2 outputs.
// Global column space (672): [0,128)=sq  [128,224)=pq  [224,352)=sk
// [352,480)=sv  [480,576)=pk  [576,672)=pv
// =====================================================================
__global__ __launch_bounds__(256) void proj_fused_kernel(
    const float* __restrict__ q_in, const float* __restrict__ kv_in,
    const float* __restrict__ w_sq, const float* __restrict__ w_pq,
    const float* __restrict__ w_sk, const float* __restrict__ w_sv,
    const float* __restrict__ w_pk, const float* __restrict__ w_pv,
    float* __restrict__ Cq, float* __restrict__ Ckv)
{
    __shared__ __align__(16) float As[16][68];   // transposed A tile [k][m]
    __shared__ __align__(16) float Ws[16][32];

    const int tid  = threadIdx.x;
    const int row0 = blockIdx.y * 64;
    const int col0 = blockIdx.x * 32;

    // segment select (uniform per block)
    const float* A; const float* W; int nseg, wcol;
    float* C; int Ctot, ccol;
    if (col0 < 128)      { A=q_in;  W=w_sq; nseg=128; wcol=col0;     C=Cq;  Ctot=224; ccol=col0; }
    else if (col0 < 224) { A=q_in;  W=w_pq; nseg=96;  wcol=col0-128; C=Cq;  Ctot=224; ccol=col0; }
    else if (col0 < 352) { A=kv_in; W=w_sk; nseg=128; wcol=col0-224; C=Ckv; Ctot=448; ccol=col0-224; }
    else if (col0 < 480) { A=kv_in; W=w_sv; nseg=128; wcol=col0-352; C=Ckv; Ctot=448; ccol=col0-224; }
    else if (col0 < 576) { A=kv_in; W=w_pk; nseg=96;  wcol=col0-480; C=Ckv; Ctot=448; ccol=col0-224; }
    else                 { A=kv_in; W=w_pv; nseg=96;  wcol=col0-576; C=Ckv; Ctot=448; ccol=col0-224; }

    const int my = tid >> 4;          // 0..15 -> rows my*4..+3
    const int nx = tid & 15;          // 0..15 -> cols nx*2..+1

    float acc[4][2];
#pragma unroll
    for (int i = 0; i < 4; ++i) { acc[i][0] = 0.f; acc[i][1] = 0.f; }

    const int lr = tid >> 2;          // loader row 0..63
    const int lk = (tid & 3) * 4;     // loader k 0,4,8,12

    for (int k0 = 0; k0 < DIMV; k0 += 16) {
        // load A tile (64x16) transposed
        float4 av = *(const float4*)(A + (size_t)(row0 + lr)*DIMV + k0 + lk);
        As[lk+0][lr] = av.x; As[lk+1][lr] = av.y;
        As[lk+2][lr] = av.z; As[lk+3][lr] = av.w;
        // load W tile (16x32)
        if (tid < 128) {
            int wk = tid >> 3, wn = (tid & 7) * 4;
            *(float4*)&Ws[wk][wn] = *(const float4*)(W + (size_t)(k0 + wk)*nseg + wcol + wn);
        }
        __syncthreads();
#pragma unroll
        for (int kk = 0; kk < 16; ++kk) {
            float4 a = *(const float4*)&As[kk][my*4];
            float2 w = *(const float2*)&Ws[kk][nx*2];
            acc[0][0] += a.x*w.x; acc[0][1] += a.x*w.y;
            acc[1][0] += a.y*w.x; acc[1][1] += a.y*w.y;
            acc[2][0] += a.z*w.x; acc[2][1] += a.z*w.y;
            acc[3][0] += a.w*w.x; acc[3][1] += a.w*w.y;
        }
        __syncthreads();
    }
#pragma unroll
    for (int i = 0; i < 4; ++i) {
        float* cr = C + (size_t)(row0 + my*4 + i)*Ctot + ccol + nx*2;
        cr[0] = acc[i][0]; cr[1] = acc[i][1];
    }
}

// =====================================================================
// Generic GEMM for output projection: C = A(1024xK) @ W(KxN) + bias
// Same tiling as above.
// =====================================================================
__global__ __launch_bounds__(256) void out_gemm_kernel(
    const float* __restrict__ A, const float* __restrict__ W,
    const float* __restrict__ bias, float* __restrict__ C,
    int N, int K)
{
    __shared__ __align__(16) float As[16][68];
    __shared__ __align__(16) float Ws[16][32];

    const int tid  = threadIdx.x;
    const int row0 = blockIdx.y * 64;
    const int col0 = blockIdx.x * 32;
    const int my = tid >> 4;
    const int nx = tid & 15;

    float acc[4][2];
#pragma unroll
    for (int i = 0; i < 4; ++i) { acc[i][0] = 0.f; acc[i][1] = 0.f; }

    const int lr = tid >> 2;
    const int lk = (tid & 3) * 4;

    for (int k0 = 0; k0 < K; k0 += 16) {
        float4 av = *(const float4*)(A + (size_t)(row0 + lr)*K + k0 + lk);
        As[lk+0][lr] = av.x; As[lk+1][lr] = av.y;
        As[lk+2][lr] = av.z; As[lk+3][lr] = av.w;
        if (tid < 128) {
            int wk = tid >> 3, wn = (tid & 7) * 4;
            *(float4*)&Ws[wk][wn] = *(const float4*)(W + (size_t)(k0 + wk)*N + col0 + wn);
        }
        __syncthreads();
#pragma unroll
        for (int kk = 0; kk < 16; ++kk) {
            float4 a = *(const float4*)&As[kk][my*4];
            float2 w = *(const float2*)&Ws[kk][nx*2];
            acc[0][0] += a.x*w.x; acc[0][1] += a.x*w.y;
            acc[1][0] += a.y*w.x; acc[1][1] += a.y*w.y;
            acc[2][0] += a.z*w.x; acc[2][1] += a.z*w.y;
            acc[3][0] += a.w*w.x; acc[3][1] += a.w*w.y;
        }
        __syncthreads();
    }
    float b0 = bias ? bias[col0 + nx*2]     : 0.f;
    float b1 = bias ? bias[col0 + nx*2 + 1] : 0.f;
#pragma unroll
    for (int i = 0; i < 4; ++i) {
        float* cr = C + (size_t)(row0 + my*4 + i)*N + col0 + nx*2;
        cr[0] = acc[i][0] + b0; cr[1] = acc[i][1] + b1;
    }
}

// ---------------- rotate + translate qp/kp/vp in place, squared norms ----
__global__ void rotate_kernel(const float* __restrict__ rot,
                              const float* __restrict__ trans)
{
    const int bn  = blockIdx.x;
    const int tid = threadIdx.x;   // 0..31: h = tid/4, d = tid%4

    float r[9], t3[3];
#pragma unroll
    for (int k = 0; k < 9; ++k) r[k] = rot[bn*9 + k];
#pragma unroll
    for (int k = 0; k < 3; ++k) t3[k] = trans[bn*3 + k];

    float* arrs[3] = { g_q  + (size_t)bn*224 + 128,
                       g_kv + (size_t)bn*448 + 256,
                       g_kv + (size_t)bn*448 + 352 };
    float sq0 = 0.f, sq1 = 0.f;
#pragma unroll
    for (int a = 0; a < 3; ++a) {
        float* base = arrs[a] + tid*3;
        float c0 = base[0], c1 = base[1], c2 = base[2];
        float o0 = c0*r[0] + c1*r[3] + c2*r[6] + t3[0];
        float o1 = c0*r[1] + c1*r[4] + c2*r[7] + t3[1];
        float o2 = c0*r[2] + c1*r[5] + c2*r[8] + t3[2];
        base[0] = o0; base[1] = o1; base[2] = o2;
        float s = o0*o0 + o1*o1 + o2*o2;
        if (a == 0) sq0 = s;
        if (a == 1) sq1 = s;
    }
#pragma unroll
    for (int off = 1; off < 4; off <<= 1) {
        sq0 += __shfl_xor_sync(0xffffffffu, sq0, off);
        sq1 += __shfl_xor_sync(0xffffffffu, sq1, off);
    }
    if ((tid & 3) == 0) {
        g_qsq[bn*8 + (tid >> 2)] = sq0;
        g_ksq[bn*8 + (tid >> 2)] = sq1;
    }
}

// =====================================================================
// Fused single-pass attention (online softmax), float4 inner loops.
// grid = TOK (one block per (b,i)), 256 threads.
// =====================================================================
__global__ __launch_bounds__(256) void ipa_attn_kernel(
    const float* __restrict__ pairwise,
    const float* __restrict__ rot,
    const float* __restrict__ trans,
    const float* __restrict__ w_pair,
    const float* __restrict__ b_pair,
    const float* __restrict__ point_w)
{
    __shared__ __align__(16) float pairT[64*132];   // stride 132 (16B-aligned rows)
    __shared__ __align__(16) float wexp[8*64];
    __shared__ __align__(16) float qs_s[128];
    __shared__ __align__(16) float qp_s[96];
    __shared__ __align__(16) float wpairT[8*128];   // transposed: [h][p]
    __shared__ float qsq_s[8];
    __shared__ float m_s[8], l_s[8], alpha_s[8], coef_s[8], bp_s[8];
    __shared__ float R_s[9], T_s[3];
    __shared__ float pts_s[96], ptsl_s[96];

    const int tid = threadIdx.x;
    const int bn  = blockIdx.x;
    const int b   = bn >> 9;

    if (tid < 128) qs_s[tid] = g_q[(size_t)bn*224 + tid];
    if (tid < 96)  qp_s[tid] = g_q[(size_t)bn*224 + 128 + tid];
    if (tid < 8) {
        qsq_s[tid] = g_qsq[bn*8 + tid];
        m_s[tid]   = -1e30f;
        l_s[tid]   = 0.f;
        bp_s[tid]  = b_pair[tid];
        float x = point_w[tid];
        coef_s[tid] = -0.5f * POINT_SCALE * log1pf(__expf(x));   // softplus
    }
#pragma unroll
    for (int l = 0; l < 4; ++l) {
        int idx = l*256 + tid;            // idx = h*128 + p
        int h = idx >> 7, p = idx & 127;
        wpairT[idx] = w_pair[p*8 + h];
    }
    if (tid < 9) R_s[tid] = rot[bn*9 + tid];
    if (tid < 3) T_s[tid] = trans[bn*3 + tid];
    __syncthreads();

    // accumulator ownership
    const int h_p  = tid >> 5;           // pair-acc head (warp)
    const int lane = tid & 31;
    float4 accp = make_float4(0.f, 0.f, 0.f, 0.f);   // p = lane*4 .. +3

    const bool has_v = tid < 224;        // 8 heads x 28 value-features
    int h_v = 0, f_v = 0;
    if (has_v) { h_v = tid / 28; f_v = tid - h_v*28; }
    float accv = 0.f;
    // value source offset within g_kv row (stride 448)
    int v_off = (f_v < 16) ? (128 + h_v*16 + f_v) : (352 + h_v*12 + (f_v - 16));

    const int jj_l = tid >> 2;           // 0..63 logit row
    const int hb_l = tid & 3;            // heads hb, hb+4

    const float* gp_base = pairwise + (size_t)bn * NN * 128;

    for (int tile = 0; tile < 8; ++tile) {
        const int j0 = tile * 64;
        // ---- load pairwise tile (64 x 128) via float4 ----
        {
            const float* gp = gp_base + (size_t)j0 * 128;
#pragma unroll
            for (int l = 0; l < 8; ++l) {
                int idx = l*256 + tid;           // float4 index
                int jj = idx >> 5, p4 = (idx & 31) * 4;
                *(float4*)&pairT[jj*132 + p4] = *(const float4*)(gp + idx*4);
            }
        }
        __syncthreads();

        // ---- logits ----
        {
            const int j = j0 + jj_l;
            const size_t bj = (size_t)b*NN + j;
            const float* pr = &pairT[jj_l*132];
            const int h0 = hb_l, h1 = hb_l + 4;

            // pair bias for both heads, float4
            float b0 = bp_s[h0], b1 = bp_s[h1];
            const float* wt0 = &wpairT[h0*128];
            const float* wt1 = &wpairT[h1*128];
#pragma unroll
            for (int p = 0; p < 128; p += 4) {
                float4 pv = *(const float4*)(pr + p);
                float4 wa = *(const float4*)(wt0 + p);
                float4 wb = *(const float4*)(wt1 + p);
                b0 += pv.x*wa.x + pv.y*wa.y + pv.z*wa.z + pv.w*wa.w;
                b1 += pv.x*wb.x + pv.y*wb.y + pv.z*wb.z + pv.w*wb.w;
            }
            const float* kvr = g_kv + bj*448;
#pragma unroll
            for (int hh = 0; hh < 2; ++hh) {
                const int h = (hh == 0) ? h0 : h1;
                // scalar qk dot (16)
                float s = 0.f;
#pragma unroll
                for (int f = 0; f < 16; f += 4) {
                    float4 kf = *(const float4*)(kvr + h*16 + f);
                    float4 qf = *(const float4*)(qs_s + h*16 + f);
                    s += qf.x*kf.x + qf.y*kf.y + qf.z*kf.z + qf.w*kf.w;
                }
                // point dot (12)
                float dt = 0.f;
#pragma unroll
                for (int e = 0; e < 12; e += 4) {
                    float4 kf = *(const float4*)(kvr + 256 + h*12 + e);
                    float4 qf = *(const float4*)(qp_s + h*12 + e);
                    dt += qf.x*kf.x + qf.y*kf.y + qf.z*kf.z + qf.w*kf.w;
                }
                float dist = qsq_s[h] + g_ksq[bj*8 + h] - 2.f*dt;
                float bias = (hh == 0) ? b0 : b1;
                wexp[h*64 + jj_l] = s*SCALAR_SCALE + bias*PAIR_SCALE + coef_s[h]*dist;
            }
        }
        __syncthreads();

        // ---- online softmax update (warp w owns head w) ----
        {
            const int w = tid >> 5;
            float v0 = wexp[w*64 + lane], v1 = wexp[w*64 + 32 + lane];
            float mx = fmaxf(v0, v1);
#pragma unroll
            for (int off = 16; off; off >>= 1)
                mx = fmaxf(mx, __shfl_xor_sync(0xffffffffu, mx, off));
            float mold = m_s[w];
            float mnew = fmaxf(mold, mx);
            float a  = __expf(mold - mnew);
            float e0 = __expf(v0 - mnew), e1 = __expf(v1 - mnew);
            wexp[w*64 + lane]      = e0;
            wexp[w*64 + 32 + lane] = e1;
            float sm = e0 + e1;
#pragma unroll
            for (int off = 16; off; off >>= 1)
                sm += __shfl_xor_sync(0xffffffffu, sm, off);
            if (lane == 0) { l_s[w] = l_s[w]*a + sm; m_s[w] = mnew; alpha_s[w] = a; }
        }
        __syncthreads();

        // ---- accumulate res_pair: warp h_p, float4 over p ----
        {
            float a = alpha_s[h_p];
            accp.x *= a; accp.y *= a; accp.z *= a; accp.w *= a;
            const float* we = &wexp[h_p*64];
            const float* rowp = &pairT[lane*4];
#pragma unroll 4
            for (int jj0 = 0; jj0 < 64; jj0 += 4) {
                float4 w4 = *(const float4*)(we + jj0);
                float4 r0 = *(const float4*)(rowp + (jj0+0)*132);
                float4 r1 = *(const float4*)(rowp + (jj0+1)*132);
                float4 r2 = *(const float4*)(rowp + (jj0+2)*132);
                float4 r3 = *(const float4*)(rowp + (jj0+3)*132);
                accp.x += w4.x*r0.x + w4.y*r1.x + w4.z*r2.x + w4.w*r3.x;
                accp.y += w4.x*r0.y + w4.y*r1.y + w4.z*r2.y + w4.w*r3.y;
                accp.z += w4.x*r0.z + w4.y*r1.z + w4.z*r2.z + w4.w*r3.z;
                accp.w += w4.x*r0.w + w4.y*r1.w + w4.z*r2.w + w4.w*r3.w;
            }
        }
        // ---- accumulate res_scalar / res_pts (threads 0..223) ----
        if (has_v) {
            float a = alpha_s[h_v];
            accv *= a;
            const float* we  = &wexp[h_v*64];
            const float* src = g_kv + ((size_t)b*NN + j0)*448 + v_off;
#pragma unroll 4
            for (int jj0 = 0; jj0 < 64; jj0 += 4) {
                float4 w4 = *(const float4*)(we + jj0);
                accv += w4.x*src[(size_t)(jj0+0)*448];
                accv += w4.y*src[(size_t)(jj0+1)*448];
                accv += w4.z*src[(size_t)(jj0+2)*448];
                accv += w4.w*src[(size_t)(jj0+3)*448];
            }
        }
        __syncthreads();
    }

    // ---- finalize ----
    float* fr = g_feats + (size_t)bn*1280;
    {
        float il = 1.0f / l_s[h_p];
        float* dst = fr + 256 + h_p*128 + lane*4;
        dst[0] = accp.x*il; dst[1] = accp.y*il;
        dst[2] = accp.z*il; dst[3] = accp.w*il;
    }
    if (has_v) {
        float il = 1.0f / l_s[h_v];
        float r = accv*il;
        if (f_v < 16) fr[h_v*16 + f_v] = r;              // res_scalar
        else          pts_s[h_v*12 + (f_v-16)] = r;      // global-frame pts
    }
    __syncthreads();
    if (tid < 96) {  // local-frame pts: out[r] = sum_c (v[c]-t[c]) * R[r*3+c]
        int hd = tid / 3, r = tid - hd*3;
        float c0 = pts_s[hd*3 + 0] - T_s[0];
        float c1 = pts_s[hd*3 + 1] - T_s[1];
        float c2 = pts_s[hd*3 + 2] - T_s[2];
        float loc = c0*R_s[r*3 + 0] + c1*R_s[r*3 + 1] + c2*R_s[r*3 + 2];
        fr[128 + tid] = loc;
        ptsl_s[tid]   = loc;
    }
    __syncthreads();
    if (tid < 32) {
        float x = ptsl_s[tid*3], y = ptsl_s[tid*3 + 1], z = ptsl_s[tid*3 + 2];
        fr[224 + tid] = sqrtf(x*x + y*y + z*z + EPSV);
    }
}

// ---------------- launcher ----------------
extern "C" void kernel_launch(void* const* d_in, const int* in_sizes, int n_in,
                              void* d_out, int out_size)
{
    const float* q_single  = (const float*)d_in[0];
    const float* kv_single = (const float*)d_in[1];
    const float* pairwise  = (const float*)d_in[2];
    const float* rot       = (const float*)d_in[3];
    const float* trans     = (const float*)d_in[4];
    // d_in[5], d_in[6]: q_mask / kv_mask (all true) - unused
    const float* w_sq   = (const float*)d_in[7];
    const float* w_sk   = (const float*)d_in[8];
    const float* w_sv   = (const float*)d_in[9];
    const float* w_pq   = (const float*)d_in[10];
    const float* w_pk   = (const float*)d_in[11];
    const float* w_pv   = (const float*)d_in[12];
    const float* w_pair = (const float*)d_in[13];
    const float* b_pair = (const float*)d_in[14];
    const float* pw     = (const float*)d_in[15];
    const float* w_out  = (const float*)d_in[16];
    const float* b_out  = (const float*)d_in[17];
    float* out = (float*)d_out;

    float *p_q, *p_kv, *p_feats;
    cudaGetSymbolAddress((void**)&p_q,  g_q);
    cudaGetSymbolAddress((void**)&p_kv, g_kv);
    cudaGetSymbolAddress((void**)&p_feats, g_feats);

    // all projections, one launch: 672 output cols -> grid (21, 16)
    proj_fused_kernel<<<dim3(21, 16), 256>>>(
        q_single, kv_single, w_sq, w_pq, w_sk, w_sv, w_pk, w_pv, p_q, p_kv);

    rotate_kernel<<<TOK, 32>>>(rot, trans);

    ipa_attn_kernel<<<TOK, 256>>>(pairwise, rot, trans, w_pair, b_pair, pw);

    // output projection: feats(1024x1280) @ w_out(1280x384) + b_out
    out_gemm_kernel<<<dim3(12, 16), 256>>>(p_feats, w_out, b_out, out, DIMV, 1280);
}

// round 3
// speedup vs baseline: 1.7247x; 1.4805x over previous
#include <cuda_runtime.h>
#include <math.h>
#include <stdint.h>

// Problem constants (fixed shapes)
#define BB   2
#define NN   512
#define DIMV 384
#define TOK  (BB*NN)          // 1024

#define SCALAR_SCALE 0.14433756729740643f   // (3*16)^-0.5
#define POINT_SCALE  0.13608276348795434f   // (3*4*4.5)^-0.5
#define PAIR_SCALE   0.57735026918962576f   // 3^-0.5
#define EPSV 1e-8f

// ---------------- device scratch ----------------
// g_q  row layout (stride 224): qs[0:128), qp[128:224)
// g_kv row layout (stride 448): ks[0:128), vs[128:256), kp[256:352), vp[352:448)
__device__ float g_q[TOK*224];
__device__ float g_kv[TOK*448];
__device__ float g_qsq[TOK*8];
__device__ float g_ksq[TOK*8];
__device__ float g_feats[TOK*1280];
__device__ float g_part[2*TOK*DIMV];

// =====================================================================
// Fused projection GEMM: all 6 projections in one launch.
// =====================================================================
__global__ __launch_bounds__(256) void proj_fused_kernel(
    const float* __restrict__ q_in, const float* __restrict__ kv_in,
    const float* __restrict__ w_sq, const float* __restrict__ w_pq,
    const float* __restrict__ w_sk, const float* __restrict__ w_sv,
    const float* __restrict__ w_pk, const float* __restrict__ w_pv,
    float* __restrict__ Cq, float* __restrict__ Ckv)
{
    __shared__ __align__(16) float As[16][68];
    __shared__ __align__(16) float Ws[16][32];

    const int tid  = threadIdx.x;
    const int row0 = blockIdx.y * 64;
    const int col0 = blockIdx.x * 32;

    const float* A; const float* W; int nseg, wcol;
    float* C; int Ctot, ccol;
    if (col0 < 128)      { A=q_in;  W=w_sq; nseg=128; wcol=col0;     C=Cq;  Ctot=224; ccol=col0; }
    else if (col0 < 224) { A=q_in;  W=w_pq; nseg=96;  wcol=col0-128; C=Cq;  Ctot=224; ccol=col0; }
    else if (col0 < 352) { A=kv_in; W=w_sk; nseg=128; wcol=col0-224; C=Ckv; Ctot=448; ccol=col0-224; }
    else if (col0 < 480) { A=kv_in; W=w_sv; nseg=128; wcol=col0-352; C=Ckv; Ctot=448; ccol=col0-224; }
    else if (col0 < 576) { A=kv_in; W=w_pk; nseg=96;  wcol=col0-480; C=Ckv; Ctot=448; ccol=col0-224; }
    else                 { A=kv_in; W=w_pv; nseg=96;  wcol=col0-576; C=Ckv; Ctot=448; ccol=col0-224; }

    const int my = tid >> 4;
    const int nx = tid & 15;

    float acc[4][2];
#pragma unroll
    for (int i = 0; i < 4; ++i) { acc[i][0] = 0.f; acc[i][1] = 0.f; }

    const int lr = tid >> 2;
    const int lk = (tid & 3) * 4;

    for (int k0 = 0; k0 < DIMV; k0 += 16) {
        float4 av = *(const float4*)(A + (size_t)(row0 + lr)*DIMV + k0 + lk);
        As[lk+0][lr] = av.x; As[lk+1][lr] = av.y;
        As[lk+2][lr] = av.z; As[lk+3][lr] = av.w;
        if (tid < 128) {
            int wk = tid >> 3, wn = (tid & 7) * 4;
            *(float4*)&Ws[wk][wn] = *(const float4*)(W + (size_t)(k0 + wk)*nseg + wcol + wn);
        }
        __syncthreads();
#pragma unroll
        for (int kk = 0; kk < 16; ++kk) {
            float4 a = *(const float4*)&As[kk][my*4];
            float2 w = *(const float2*)&Ws[kk][nx*2];
            acc[0][0] += a.x*w.x; acc[0][1] += a.x*w.y;
            acc[1][0] += a.y*w.x; acc[1][1] += a.y*w.y;
            acc[2][0] += a.z*w.x; acc[2][1] += a.z*w.y;
            acc[3][0] += a.w*w.x; acc[3][1] += a.w*w.y;
        }
        __syncthreads();
    }
#pragma unroll
    for (int i = 0; i < 4; ++i) {
        float* cr = C + (size_t)(row0 + my*4 + i)*Ctot + ccol + nx*2;
        cr[0] = acc[i][0]; cr[1] = acc[i][1];
    }
}

// =====================================================================
// Output GEMM, K split in two halves via blockIdx.z.
// P[z] = A(1024 x 1280, half-K) @ W(1280 x 384)
// =====================================================================
__global__ __launch_bounds__(256) void out_gemm_part(
    const float* __restrict__ A, const float* __restrict__ W,
    float* __restrict__ P)
{
    __shared__ __align__(16) float As[16][68];
    __shared__ __align__(16) float Ws[16][32];

    const int tid  = threadIdx.x;
    const int row0 = blockIdx.y * 64;
    const int col0 = blockIdx.x * 32;
    const int kh   = blockIdx.z;
    const int my = tid >> 4;
    const int nx = tid & 15;

    float acc[4][2];
#pragma unroll
    for (int i = 0; i < 4; ++i) { acc[i][0] = 0.f; acc[i][1] = 0.f; }

    const int lr = tid >> 2;
    const int lk = (tid & 3) * 4;
    const int kbeg = kh * 640, kend = kbeg + 640;

    for (int k0 = kbeg; k0 < kend; k0 += 16) {
        float4 av = *(const float4*)(A + (size_t)(row0 + lr)*1280 + k0 + lk);
        As[lk+0][lr] = av.x; As[lk+1][lr] = av.y;
        As[lk+2][lr] = av.z; As[lk+3][lr] = av.w;
        if (tid < 128) {
            int wk = tid >> 3, wn = (tid & 7) * 4;
            *(float4*)&Ws[wk][wn] = *(const float4*)(W + (size_t)(k0 + wk)*DIMV + col0 + wn);
        }
        __syncthreads();
#pragma unroll
        for (int kk = 0; kk < 16; ++kk) {
            float4 a = *(const float4*)&As[kk][my*4];
            float2 w = *(const float2*)&Ws[kk][nx*2];
            acc[0][0] += a.x*w.x; acc[0][1] += a.x*w.y;
            acc[1][0] += a.y*w.x; acc[1][1] += a.y*w.y;
            acc[2][0] += a.z*w.x; acc[2][1] += a.z*w.y;
            acc[3][0] += a.w*w.x; acc[3][1] += a.w*w.y;
        }
        __syncthreads();
    }
    float* dst = P + (size_t)kh*TOK*DIMV;
#pragma unroll
    for (int i = 0; i < 4; ++i) {
        float* cr = dst + (size_t)(row0 + my*4 + i)*DIMV + col0 + nx*2;
        cr[0] = acc[i][0]; cr[1] = acc[i][1];
    }
}

__global__ __launch_bounds__(256) void add_bias_kernel(
    const float* __restrict__ bias, float* __restrict__ out)
{
    int idx = blockIdx.x * 256 + threadIdx.x;   // 1024*384 total
    out[idx] = g_part[idx] + g_part[TOK*DIMV + idx] + bias[idx % DIMV];
}

// ---------------- rotate + translate qp/kp/vp in place, squared norms ----
__global__ void rotate_kernel(const float* __restrict__ rot,
                              const float* __restrict__ trans)
{
    const int bn  = blockIdx.x;
    const int tid = threadIdx.x;   // 0..31: h = tid/4, d = tid%4

    float r[9], t3[3];
#pragma unroll
    for (int k = 0; k < 9; ++k) r[k] = rot[bn*9 + k];
#pragma unroll
    for (int k = 0; k < 3; ++k) t3[k] = trans[bn*3 + k];

    float* arrs[3] = { g_q  + (size_t)bn*224 + 128,
                       g_kv + (size_t)bn*448 + 256,
                       g_kv + (size_t)bn*448 + 352 };
    float sq0 = 0.f, sq1 = 0.f;
#pragma unroll
    for (int a = 0; a < 3; ++a) {
        float* base = arrs[a] + tid*3;
        float c0 = base[0], c1 = base[1], c2 = base[2];
        float o0 = c0*r[0] + c1*r[3] + c2*r[6] + t3[0];
        float o1 = c0*r[1] + c1*r[4] + c2*r[7] + t3[1];
        float o2 = c0*r[2] + c1*r[5] + c2*r[8] + t3[2];
        base[0] = o0; base[1] = o1; base[2] = o2;
        float s = o0*o0 + o1*o1 + o2*o2;
        if (a == 0) sq0 = s;
        if (a == 1) sq1 = s;
    }
#pragma unroll
    for (int off = 1; off < 4; off <<= 1) {
        sq0 += __shfl_xor_sync(0xffffffffu, sq0, off);
        sq1 += __shfl_xor_sync(0xffffffffu, sq1, off);
    }
    if ((tid & 3) == 0) {
        g_qsq[bn*8 + (tid >> 2)] = sq0;
        g_ksq[bn*8 + (tid >> 2)] = sq1;
    }
}

// =====================================================================
// Fused single-pass attention, warp-specialized phases.
// grid = TOK (one block per (b,i)), 256 threads.
// =====================================================================
__global__ __launch_bounds__(256) void ipa_attn_kernel(
    const float* __restrict__ pairwise,
    const float* __restrict__ rot,
    const float* __restrict__ trans,
    const float* __restrict__ w_pair,
    const float* __restrict__ b_pair,
    const float* __restrict__ point_w)
{
    __shared__ __align__(16) float pairT[64*132];   // 33 KB
    __shared__ __align__(16) float pbias[2*64*8];   // 4 KB  [phalf][jj][h]
    __shared__ __align__(16) float wexp[8*64];      // 2 KB  [h][jj]
    __shared__ __align__(16) float wpm[128*8];      // 4 KB  [p][h]
    __shared__ __align__(16) float qs_s[128];
    __shared__ __align__(16) float qp_s[96];
    __shared__ float qsq_s[8];
    __shared__ float m_s[8], l_s[8], alpha_s[8], coef_s[8], bp_s[8];
    __shared__ float R_s[9], T_s[3];
    __shared__ float pts_s[96], ptsl_s[96];

    const int tid  = threadIdx.x;
    const int bn   = blockIdx.x;
    const int b    = bn >> 9;
    const int w    = tid >> 5;
    const int lane = tid & 31;

    if (tid < 128) qs_s[tid] = g_q[(size_t)bn*224 + tid];
    if (tid < 96)  qp_s[tid] = g_q[(size_t)bn*224 + 128 + tid];
    if (tid < 8) {
        qsq_s[tid] = g_qsq[bn*8 + tid];
        m_s[tid]   = -1e30f;
        l_s[tid]   = 0.f;
        bp_s[tid]  = b_pair[tid];
        float x = point_w[tid];
        coef_s[tid] = -0.5f * POINT_SCALE * log1pf(__expf(x));   // softplus
    }
#pragma unroll
    for (int l = 0; l < 4; ++l) wpm[l*256 + tid] = w_pair[l*256 + tid];  // [p][h]
    if (tid < 9) R_s[tid] = rot[bn*9 + tid];
    if (tid < 3) T_s[tid] = trans[bn*3 + tid];
    __syncthreads();

    // persistent accumulators
    float4 accp0 = make_float4(0.f,0.f,0.f,0.f);   // res_pair h0, p = lane*4..
    float4 accp1 = make_float4(0.f,0.f,0.f,0.f);   // res_pair h1
    float accvs = 0.f, accvp = 0.f;                // value warps
    int h_vs = 0, f_vs = 0, h_vp = 0, f_vp = 0;
    bool vp_act = false;
    if (w >= 4) {
        int k = w - 4;
        if (lane < 16) { h_vs = 2*k;     f_vs = lane; }
        else           { h_vs = 2*k + 1; f_vs = lane - 16; }
        if (lane < 12)       { h_vp = 2*k;     f_vp = lane;      vp_act = true; }
        else if (lane < 24)  { h_vp = 2*k + 1; f_vp = lane - 12; vp_act = true; }
    }

    const float* gp_base = pairwise + (size_t)bn * NN * 128;

    for (int tile = 0; tile < 8; ++tile) {
        const int j0 = tile * 64;
        // ---- load pairwise tile (64 x 128) ----
        {
            const float* gp = gp_base + (size_t)j0 * 128;
#pragma unroll
            for (int l = 0; l < 8; ++l) {
                int idx = l*256 + tid;
                int jj = idx >> 5, p4 = (idx & 31) * 4;
                *(float4*)&pairT[jj*132 + p4] = *(const float4*)(gp + idx*4);
            }
        }
        __syncthreads();

        if (w < 4) {
            // ---- bias partials: lane = jj, warp owns 64-p half, 8 heads in regs ----
            const int jhalf = w >> 1, phalf = w & 1;
            const int jj = jhalf*32 + lane;
            float acc[8];
#pragma unroll
            for (int h = 0; h < 8; ++h) acc[h] = 0.f;
            const float* prow = &pairT[jj*132 + phalf*64];
            const float* wrow = &wpm[phalf*64*8];
#pragma unroll
            for (int p4 = 0; p4 < 64; p4 += 4) {
                float4 pv = *(const float4*)(prow + p4);
                const float* wp = wrow + p4*8;
                float pe[4] = { pv.x, pv.y, pv.z, pv.w };
#pragma unroll
                for (int e = 0; e < 4; ++e) {
                    float4 wa = *(const float4*)(wp + e*8);       // broadcast
                    float4 wb = *(const float4*)(wp + e*8 + 4);   // broadcast
                    acc[0] += pe[e]*wa.x; acc[1] += pe[e]*wa.y;
                    acc[2] += pe[e]*wa.z; acc[3] += pe[e]*wa.w;
                    acc[4] += pe[e]*wb.x; acc[5] += pe[e]*wb.y;
                    acc[6] += pe[e]*wb.z; acc[7] += pe[e]*wb.w;
                }
            }
            float* pb = &pbias[phalf*512 + jj*8];
            *(float4*)pb       = make_float4(acc[0], acc[1], acc[2], acc[3]);
            *(float4*)(pb + 4) = make_float4(acc[4], acc[5], acc[6], acc[7]);
        } else {
            // ---- z-base: qk + point dist, 4 heads per thread ----
            const int wq = w - 4;
            const int jj = wq*16 + (lane >> 1);
            const int hb = (lane & 1) * 4;
            const size_t bj = (size_t)b*NN + j0 + jj;
            const float* kvr = g_kv + bj*448;
            const float* kq  = g_ksq + bj*8;
#pragma unroll
            for (int i = 0; i < 4; ++i) {
                int h = hb + i;
                float s = 0.f, dt = 0.f;
#pragma unroll
                for (int f = 0; f < 16; f += 4) {
                    float4 kf = *(const float4*)(kvr + h*16 + f);
                    float4 qf = *(const float4*)(qs_s + h*16 + f);
                    s += qf.x*kf.x + qf.y*kf.y + qf.z*kf.z + qf.w*kf.w;
                }
#pragma unroll
                for (int e = 0; e < 12; e += 4) {
                    float4 kf = *(const float4*)(kvr + 256 + h*12 + e);
                    float4 qf = *(const float4*)(qp_s + h*12 + e);
                    dt += qf.x*kf.x + qf.y*kf.y + qf.z*kf.z + qf.w*kf.w;
                }
                float dist = qsq_s[h] + kq[h] - 2.f*dt;
                wexp[h*64 + jj] = s*SCALAR_SCALE + bp_s[h]*PAIR_SCALE + coef_s[h]*dist;
            }
        }
        __syncthreads();

        // ---- combine bias partials into logits ----
        {
            const int jj = tid >> 2, hp = tid & 3;
            float b0 = pbias[jj*8 + hp]     + pbias[512 + jj*8 + hp];
            float b1 = pbias[jj*8 + hp + 4] + pbias[512 + jj*8 + hp + 4];
            wexp[hp*64 + jj]       += PAIR_SCALE * b0;
            wexp[(hp+4)*64 + jj]   += PAIR_SCALE * b1;
        }
        __syncthreads();

        // ---- online softmax update (warp w owns head w) ----
        {
            float v0 = wexp[w*64 + lane], v1 = wexp[w*64 + 32 + lane];
            float mx = fmaxf(v0, v1);
#pragma unroll
            for (int off = 16; off; off >>= 1)
                mx = fmaxf(mx, __shfl_xor_sync(0xffffffffu, mx, off));
            float mold = m_s[w];
            float mnew = fmaxf(mold, mx);
            float a  = __expf(mold - mnew);
            float e0 = __expf(v0 - mnew), e1 = __expf(v1 - mnew);
            wexp[w*64 + lane]      = e0;
            wexp[w*64 + 32 + lane] = e1;
            float sm = e0 + e1;
#pragma unroll
            for (int off = 16; off; off >>= 1)
                sm += __shfl_xor_sync(0xffffffffu, sm, off);
            if (lane == 0) { l_s[w] = l_s[w]*a + sm; m_s[w] = mnew; alpha_s[w] = a; }
        }
        __syncthreads();

        if (w < 4) {
            // ---- res_pair: 2 heads per warp, p-quad per lane ----
            const int h0 = 2*w, h1 = 2*w + 1;
            float a0 = alpha_s[h0], a1 = alpha_s[h1];
            accp0.x *= a0; accp0.y *= a0; accp0.z *= a0; accp0.w *= a0;
            accp1.x *= a1; accp1.y *= a1; accp1.z *= a1; accp1.w *= a1;
            const float* we0 = &wexp[h0*64];
            const float* we1 = &wexp[h1*64];
            const float* rowp = &pairT[lane*4];
#pragma unroll 4
            for (int jj0 = 0; jj0 < 64; jj0 += 4) {
                float4 wA = *(const float4*)(we0 + jj0);   // broadcast
                float4 wB = *(const float4*)(we1 + jj0);   // broadcast
                float4 r0 = *(const float4*)(rowp + (jj0+0)*132);
                float4 r1 = *(const float4*)(rowp + (jj0+1)*132);
                float4 r2 = *(const float4*)(rowp + (jj0+2)*132);
                float4 r3 = *(const float4*)(rowp + (jj0+3)*132);
                accp0.x += wA.x*r0.x + wA.y*r1.x + wA.z*r2.x + wA.w*r3.x;
                accp0.y += wA.x*r0.y + wA.y*r1.y + wA.z*r2.y + wA.w*r3.y;
                accp0.z += wA.x*r0.z + wA.y*r1.z + wA.z*r2.z + wA.w*r3.z;
                accp0.w += wA.x*r0.w + wA.y*r1.w + wA.z*r2.w + wA.w*r3.w;
                accp1.x += wB.x*r0.x + wB.y*r1.x + wB.z*r2.x + wB.w*r3.x;
                accp1.y += wB.x*r0.y + wB.y*r1.y + wB.z*r2.y + wB.w*r3.y;
                accp1.z += wB.x*r0.z + wB.y*r1.z + wB.z*r2.z + wB.w*r3.z;
                accp1.w += wB.x*r0.w + wB.y*r1.w + wB.z*r2.w + wB.w*r3.w;
            }
        } else {
            // ---- value accumulation ----
            float aS = alpha_s[h_vs];
            accvs *= aS;
            if (vp_act) accvp *= alpha_s[h_vp];
            const size_t base = ((size_t)b*NN + j0)*448;
            const float* svs = g_kv + base + 128 + h_vs*16 + f_vs;
            const float* svp = g_kv + base + 352 + h_vp*12 + f_vp;
            const float* weS = &wexp[h_vs*64];
            const float* weP = &wexp[h_vp*64];
#pragma unroll 4
            for (int jj0 = 0; jj0 < 64; jj0 += 4) {
                float4 w4 = *(const float4*)(weS + jj0);
                accvs += w4.x*svs[(size_t)(jj0+0)*448] + w4.y*svs[(size_t)(jj0+1)*448]
                       + w4.z*svs[(size_t)(jj0+2)*448] + w4.w*svs[(size_t)(jj0+3)*448];
                if (vp_act) {
                    float4 w5 = *(const float4*)(weP + jj0);
                    accvp += w5.x*svp[(size_t)(jj0+0)*448] + w5.y*svp[(size_t)(jj0+1)*448]
                           + w5.z*svp[(size_t)(jj0+2)*448] + w5.w*svp[(size_t)(jj0+3)*448];
                }
            }
        }
        __syncthreads();
    }

    // ---- finalize ----
    float* fr = g_feats + (size_t)bn*1280;
    if (w < 4) {
        const int h0 = 2*w, h1 = 2*w + 1;
        float il0 = 1.0f / l_s[h0], il1 = 1.0f / l_s[h1];
        float* d0 = fr + 256 + h0*128 + lane*4;
        d0[0] = accp0.x*il0; d0[1] = accp0.y*il0;
        d0[2] = accp0.z*il0; d0[3] = accp0.w*il0;
        float* d1 = fr + 256 + h1*128 + lane*4;
        d1[0] = accp1.x*il1; d1[1] = accp1.y*il1;
        d1[2] = accp1.z*il1; d1[3] = accp1.w*il1;
    } else {
        fr[h_vs*16 + f_vs] = accvs / l_s[h_vs];
        if (vp_act) pts_s[h_vp*12 + f_vp] = accvp / l_s[h_vp];
    }
    __syncthreads();
    if (tid < 96) {  // local-frame pts: out[r] = sum_c (v[c]-t[c]) * R[r*3+c]
        int hd = tid / 3, r = tid - hd*3;
        float c0 = pts_s[hd*3 + 0] - T_s[0];
        float c1 = pts_s[hd*3 + 1] - T_s[1];
        float c2 = pts_s[hd*3 + 2] - T_s[2];
        float loc = c0*R_s[r*3 + 0] + c1*R_s[r*3 + 1] + c2*R_s[r*3 + 2];
        fr[128 + tid] = loc;
        ptsl_s[tid]   = loc;
    }
    __syncthreads();
    if (tid < 32) {
        float x = ptsl_s[tid*3], y = ptsl_s[tid*3 + 1], z = ptsl_s[tid*3 + 2];
        fr[224 + tid] = sqrtf(x*x + y*y + z*z + EPSV);
    }
}

// ---------------- launcher ----------------
extern "C" void kernel_launch(void* const* d_in, const int* in_sizes, int n_in,
                              void* d_out, int out_size)
{
    const float* q_single  = (const float*)d_in[0];
    const float* kv_single = (const float*)d_in[1];
    const float* pairwise  = (const float*)d_in[2];
    const float* rot       = (const float*)d_in[3];
    const float* trans     = (const float*)d_in[4];
    // d_in[5], d_in[6]: q_mask / kv_mask (all true) - unused
    const float* w_sq   = (const float*)d_in[7];
    const float* w_sk   = (const float*)d_in[8];
    const float* w_sv   = (const float*)d_in[9];
    const float* w_pq   = (const float*)d_in[10];
    const float* w_pk   = (const float*)d_in[11];
    const float* w_pv   = (const float*)d_in[12];
    const float* w_pair = (const float*)d_in[13];
    const float* b_pair = (const float*)d_in[14];
    const float* pw     = (const float*)d_in[15];
    const float* w_out  = (const float*)d_in[16];
    const float* b_out  = (const float*)d_in[17];
    float* out = (float*)d_out;

    float *p_q, *p_kv, *p_feats, *p_part;
    cudaGetSymbolAddress((void**)&p_q,  g_q);
    cudaGetSymbolAddress((void**)&p_kv, g_kv);
    cudaGetSymbolAddress((void**)&p_feats, g_feats);
    cudaGetSymbolAddress((void**)&p_part, g_part);

    // all projections, one launch: 672 output cols -> grid (21, 16)
    proj_fused_kernel<<<dim3(21, 16), 256>>>(
        q_single, kv_single, w_sq, w_pq, w_sk, w_sv, w_pk, w_pv, p_q, p_kv);

    rotate_kernel<<<TOK, 32>>>(rot, trans);

    ipa_attn_kernel<<<TOK, 256>>>(pairwise, rot, trans, w_pair, b_pair, pw);

    // output projection, K split in 2: feats(1024x1280) @ w_out(1280x384)
    out_gemm_part<<<dim3(12, 16, 2), 256>>>(p_feats, w_out, p_part);
    add_bias_kernel<<<TOK*DIMV/256, 256>>>(b_out, out);
}

// round 5
// speedup vs baseline: 2.2923x; 1.3291x over previous
#include <cuda_runtime.h>
#include <math.h>
#include <stdint.h>

// Problem constants (fixed shapes)
#define BB   2
#define NN   512
#define DIMV 384
#define TOK  (BB*NN)          // 1024

#define SCALAR_SCALE 0.14433756729740643f   // (3*16)^-0.5
#define POINT_SCALE  0.13608276348795434f   // (3*4*4.5)^-0.5
#define PAIR_SCALE   0.57735026918962576f   // 3^-0.5
#define EPSV 1e-8f

// attention tiling
#define IT 4      // queries per block
#define JT 32     // keys per tile

// ---------------- device scratch ----------------
// g_q  row layout (stride 224): qs[0:128), qp[128:224)
// g_kv row layout (stride 448): ks[0:128), vs[128:256), kp[256:352), vp[352:448)
__device__ float g_q[TOK*224];
__device__ float g_kv[TOK*448];
__device__ float g_qsq[TOK*8];
__device__ float g_ksq[TOK*8];
__device__ float g_feats[TOK*1280];
__device__ float g_part[4*TOK*DIMV];

// =====================================================================
// Fused projection GEMM: all 6 projections in one launch.
// =====================================================================
__global__ __launch_bounds__(256) void proj_fused_kernel(
    const float* __restrict__ q_in, const float* __restrict__ kv_in,
    const float* __restrict__ w_sq, const float* __restrict__ w_pq,
    const float* __restrict__ w_sk, const float* __restrict__ w_sv,
    const float* __restrict__ w_pk, const float* __restrict__ w_pv,
    float* __restrict__ Cq, float* __restrict__ Ckv)
{
    __shared__ __align__(16) float As[16][68];
    __shared__ __align__(16) float Ws[16][32];

    const int tid  = threadIdx.x;
    const int row0 = blockIdx.y * 64;
    const int col0 = blockIdx.x * 32;

    const float* A; const float* W; int nseg, wcol;
    float* C; int Ctot, ccol;
    if (col0 < 128)      { A=q_in;  W=w_sq; nseg=128; wcol=col0;     C=Cq;  Ctot=224; ccol=col0; }
    else if (col0 < 224) { A=q_in;  W=w_pq; nseg=96;  wcol=col0-128; C=Cq;  Ctot=224; ccol=col0; }
    else if (col0 < 352) { A=kv_in; W=w_sk; nseg=128; wcol=col0-224; C=Ckv; Ctot=448; ccol=col0-224; }
    else if (col0 < 480) { A=kv_in; W=w_sv; nseg=128; wcol=col0-352; C=Ckv; Ctot=448; ccol=col0-224; }
    else if (col0 < 576) { A=kv_in; W=w_pk; nseg=96;  wcol=col0-480; C=Ckv; Ctot=448; ccol=col0-224; }
    else                 { A=kv_in; W=w_pv; nseg=96;  wcol=col0-576; C=Ckv; Ctot=448; ccol=col0-224; }

    const int my = tid >> 4;
    const int nx = tid & 15;

    float acc[4][2];
#pragma unroll
    for (int i = 0; i < 4; ++i) { acc[i][0] = 0.f; acc[i][1] = 0.f; }

    const int lr = tid >> 2;
    const int lk = (tid & 3) * 4;

    for (int k0 = 0; k0 < DIMV; k0 += 16) {
        float4 av = *(const float4*)(A + (size_t)(row0 + lr)*DIMV + k0 + lk);
        As[lk+0][lr] = av.x; As[lk+1][lr] = av.y;
        As[lk+2][lr] = av.z; As[lk+3][lr] = av.w;
        if (tid < 128) {
            int wk = tid >> 3, wn = (tid & 7) * 4;
            *(float4*)&Ws[wk][wn] = *(const float4*)(W + (size_t)(k0 + wk)*nseg + wcol + wn);
        }
        __syncthreads();
#pragma unroll
        for (int kk = 0; kk < 16; ++kk) {
            float4 a = *(const float4*)&As[kk][my*4];
            float2 w = *(const float2*)&Ws[kk][nx*2];
            acc[0][0] += a.x*w.x; acc[0][1] += a.x*w.y;
            acc[1][0] += a.y*w.x; acc[1][1] += a.y*w.y;
            acc[2][0] += a.z*w.x; acc[2][1] += a.z*w.y;
            acc[3][0] += a.w*w.x; acc[3][1] += a.w*w.y;
        }
        __syncthreads();
    }
#pragma unroll
    for (int i = 0; i < 4; ++i) {
        float* cr = C + (size_t)(row0 + my*4 + i)*Ctot + ccol + nx*2;
        cr[0] = acc[i][0]; cr[1] = acc[i][1];
    }
}

// =====================================================================
// Output GEMM, K split in 4 via blockIdx.z.
// =====================================================================
__global__ __launch_bounds__(256) void out_gemm_part(
    const float* __restrict__ A, const float* __restrict__ W,
    float* __restrict__ P)
{
    __shared__ __align__(16) float As[16][68];
    __shared__ __align__(16) float Ws[16][32];

    const int tid  = threadIdx.x;
    const int row0 = blockIdx.y * 64;
    const int col0 = blockIdx.x * 32;
    const int kh   = blockIdx.z;
    const int my = tid >> 4;
    const int nx = tid & 15;

    float acc[4][2];
#pragma unroll
    for (int i = 0; i < 4; ++i) { acc[i][0] = 0.f; acc[i][1] = 0.f; }

    const int lr = tid >> 2;
    const int lk = (tid & 3) * 4;
    const int kbeg = kh * 320, kend = kbeg + 320;

    for (int k0 = kbeg; k0 < kend; k0 += 16) {
        float4 av = *(const float4*)(A + (size_t)(row0 + lr)*1280 + k0 + lk);
        As[lk+0][lr] = av.x; As[lk+1][lr] = av.y;
        As[lk+2][lr] = av.z; As[lk+3][lr] = av.w;
        if (tid < 128) {
            int wk = tid >> 3, wn = (tid & 7) * 4;
            *(float4*)&Ws[wk][wn] = *(const float4*)(W + (size_t)(k0 + wk)*DIMV + col0 + wn);
        }
        __syncthreads();
#pragma unroll
        for (int kk = 0; kk < 16; ++kk) {
            float4 a = *(const float4*)&As[kk][my*4];
            float2 w = *(const float2*)&Ws[kk][nx*2];
            acc[0][0] += a.x*w.x; acc[0][1] += a.x*w.y;
            acc[1][0] += a.y*w.x; acc[1][1] += a.y*w.y;
            acc[2][0] += a.z*w.x; acc[2][1] += a.z*w.y;
            acc[3][0] += a.w*w.x; acc[3][1] += a.w*w.y;
        }
        __syncthreads();
    }
    float* dst = P + (size_t)kh*TOK*DIMV;
#pragma unroll
    for (int i = 0; i < 4; ++i) {
        float* cr = dst + (size_t)(row0 + my*4 + i)*DIMV + col0 + nx*2;
        cr[0] = acc[i][0]; cr[1] = acc[i][1];
    }
}

__global__ __launch_bounds__(256) void add_bias_kernel(
    const float* __restrict__ bias, float* __restrict__ out)
{
    int idx = blockIdx.x * 256 + threadIdx.x;   // 1024*384 total
    const int S = TOK*DIMV;
    out[idx] = g_part[idx] + g_part[S + idx] + g_part[2*S + idx]
             + g_part[3*S + idx] + bias[idx % DIMV];
}

// ---------------- rotate + translate qp/kp/vp in place, squared norms ----
__global__ void rotate_kernel(const float* __restrict__ rot,
                              const float* __restrict__ trans)
{
    const int bn  = blockIdx.x;
    const int tid = threadIdx.x;   // 0..31: h = tid/4, d = tid%4

    float r[9], t3[3];
#pragma unroll
    for (int k = 0; k < 9; ++k) r[k] = rot[bn*9 + k];
#pragma unroll
    for (int k = 0; k < 3; ++k) t3[k] = trans[bn*3 + k];

    float* arrs[3] = { g_q  + (size_t)bn*224 + 128,
                       g_kv + (size_t)bn*448 + 256,
                       g_kv + (size_t)bn*448 + 352 };
    float sq0 = 0.f, sq1 = 0.f;
#pragma unroll
    for (int a = 0; a < 3; ++a) {
        float* base = arrs[a] + tid*3;
        float c0 = base[0], c1 = base[1], c2 = base[2];
        float o0 = c0*r[0] + c1*r[3] + c2*r[6] + t3[0];
        float o1 = c0*r[1] + c1*r[4] + c2*r[7] + t3[1];
        float o2 = c0*r[2] + c1*r[5] + c2*r[8] + t3[2];
        base[0] = o0; base[1] = o1; base[2] = o2;
        float s = o0*o0 + o1*o1 + o2*o2;
        if (a == 0) sq0 = s;
        if (a == 1) sq1 = s;
    }
#pragma unroll
    for (int off = 1; off < 4; off <<= 1) {
        sq0 += __shfl_xor_sync(0xffffffffu, sq0, off);
        sq1 += __shfl_xor_sync(0xffffffffu, sq1, off);
    }
    if ((tid & 3) == 0) {
        g_qsq[bn*8 + (tid >> 2)] = sq0;
        g_ksq[bn*8 + (tid >> 2)] = sq1;
    }
}

// =====================================================================
// Fused attention: 4 queries per block, j-tile 32, dynamic smem.
// grid = 256 (BB * NN/4), 256 threads.
// =====================================================================
// smem float offsets
#define OF_PAIR  0                      // 128 rows x 132
#define OF_WEXP  16896                  // [ii][h][jj] 4*8*32
#define OF_PBIAS 17920                  // [row][h]    128*8
#define OF_WPM   18944                  // [p][h]      128*8 (pre-scaled)
#define OF_QS    19968                  // [ii][128]
#define OF_QP    20480                  // [ii][96]
#define OF_QSQ   20864                  // [ii][8]
#define OF_M     20896                  // [ii][8]
#define OF_L     20928
#define OF_ALPHA 20960
#define OF_COEF  20992                  // [8]
#define OF_BP    21000                  // [8]
#define OF_R     21008                  // [ii][9]
#define OF_T     21044                  // [ii][3]
#define OF_PTS   21056                  // [ii][96]
#define OF_PTSL  21440                  // [ii][96]
#define SM_FLOATS 21824
#define SM_BYTES (SM_FLOATS*4)

__global__ __launch_bounds__(256) void ipa_attn_kernel(
    const float* __restrict__ pairwise,
    const float* __restrict__ rot,
    const float* __restrict__ trans,
    const float* __restrict__ w_pair,
    const float* __restrict__ b_pair,
    const float* __restrict__ point_w)
{
    extern __shared__ __align__(16) float sm[];
    float* pairT = sm + OF_PAIR;
    float* wexp  = sm + OF_WEXP;
    float* pbias = sm + OF_PBIAS;
    float* wpm   = sm + OF_WPM;
    float* qs_s  = sm + OF_QS;
    float* qp_s  = sm + OF_QP;
    float* qsq_s = sm + OF_QSQ;
    float* m_s   = sm + OF_M;
    float* l_s   = sm + OF_L;
    float* al_s  = sm + OF_ALPHA;
    float* cf_s  = sm + OF_COEF;
    float* bp_s  = sm + OF_BP;
    float* R_s   = sm + OF_R;
    float* T_s   = sm + OF_T;
    float* pts_s = sm + OF_PTS;
    float* ptl_s = sm + OF_PTSL;

    const int tid  = threadIdx.x;
    const int bid  = blockIdx.x;
    const int b    = bid >> 7;
    const int i0   = (bid & 127) * IT;
    const int w    = tid >> 5;
    const int lane = tid & 31;

    // ---- prologue loads ----
#pragma unroll
    for (int l = 0; l < 2; ++l) {             // qs: 512 floats
        int idx = l*256 + tid;
        int ii = idx >> 7;
        qs_s[idx] = g_q[(size_t)(b*NN + i0 + ii)*224 + (idx & 127)];
    }
#pragma unroll
    for (int idx = tid; idx < IT*96; idx += 256) {   // qp: 384 floats (FIXED)
        int ii = idx / 96;
        qp_s[idx] = g_q[(size_t)(b*NN + i0 + ii)*224 + 128 + (idx % 96)];
    }
    if (tid < 32) {
        int ii = tid >> 3;
        qsq_s[tid] = g_qsq[(size_t)(b*NN + i0 + ii)*8 + (tid & 7)];
        m_s[tid] = -1e30f;
        l_s[tid] = 0.f;
    }
    if (tid < 8) {
        bp_s[tid] = b_pair[tid] * PAIR_SCALE;
        float x = point_w[tid];
        cf_s[tid] = -0.5f * POINT_SCALE * log1pf(__expf(x));
    }
#pragma unroll
    for (int l = 0; l < 4; ++l) wpm[l*256 + tid] = w_pair[l*256 + tid] * PAIR_SCALE;
    if (tid >= 64 && tid < 100) {             // R: 36
        int idx = tid - 64;
        int ii = idx / 9;
        R_s[idx] = rot[(size_t)(b*NN + i0 + ii)*9 + (idx % 9)];
    }
    if (tid >= 100 && tid < 112) {            // T: 12
        int idx = tid - 100;
        int ii = idx / 3;
        T_s[idx] = trans[(size_t)(b*NN + i0 + ii)*3 + (idx % 3)];
    }
    __syncthreads();

    // persistent accumulators
    float4 a0[IT], a1[IT];                    // res_pair (warps 0-3): heads 2w,2w+1
#pragma unroll
    for (int ii = 0; ii < IT; ++ii) { a0[ii] = make_float4(0,0,0,0); a1[ii] = make_float4(0,0,0,0); }
    float accs[IT] = {0,0,0,0}, accp[IT] = {0,0,0,0};   // value (warps 4-7)
    const int tv = tid - 128;                 // 0..127 for warps 4-7
    const int hs = (tv >= 0) ? (tv >> 4) : 0;
    const int fs = (tv >= 0) ? (tv & 15) : 0;
    const bool vp_act = (tv >= 0) && (tv < 96);
    const int hp = vp_act ? (tv / 12) : 0;
    const int fp = vp_act ? (tv % 12) : 0;

    const float* gp_base = pairwise + ((size_t)b*NN + i0) * NN * 128;

    for (int tile = 0; tile < 16; ++tile) {
        const int j0 = tile * JT;
        // ---- load pair tiles: 4 ii x 32 jj x 128 p ----
        {
#pragma unroll
            for (int l = 0; l < 16; ++l) {
                int idx = l*256 + tid;              // float4 index, 4096 total
                int ii  = idx >> 10;
                int rem = idx & 1023;
                int jj  = rem >> 5;
                int p4  = (rem & 31) * 4;
                *(float4*)&pairT[(ii*JT + jj)*132 + p4] =
                    *(const float4*)(gp_base + ((size_t)ii*NN + j0 + jj)*128 + p4);
            }
        }
        __syncthreads();

        // ---- phase A ----
        if (tid < 128) {
            // bias: row = (ii,jj), all 8 heads, full p
            const int row = tid;
            const float* prow = &pairT[row*132];
            float acc[8];
#pragma unroll
            for (int h = 0; h < 8; ++h) acc[h] = 0.f;
#pragma unroll 8
            for (int p4 = 0; p4 < 128; p4 += 4) {
                float4 pv = *(const float4*)(prow + p4);
                float pe[4] = { pv.x, pv.y, pv.z, pv.w };
#pragma unroll
                for (int e = 0; e < 4; ++e) {
                    float4 wa = *(const float4*)&wpm[(p4+e)*8];
                    float4 wb = *(const float4*)&wpm[(p4+e)*8 + 4];
                    acc[0] += pe[e]*wa.x; acc[1] += pe[e]*wa.y;
                    acc[2] += pe[e]*wa.z; acc[3] += pe[e]*wa.w;
                    acc[4] += pe[e]*wb.x; acc[5] += pe[e]*wb.y;
                    acc[6] += pe[e]*wb.z; acc[7] += pe[e]*wb.w;
                }
            }
            *(float4*)&pbias[row*8]     = make_float4(acc[0], acc[1], acc[2], acc[3]);
            *(float4*)&pbias[row*8 + 4] = make_float4(acc[4], acc[5], acc[6], acc[7]);
        } else {
            // z-base: t -> (jj, head-quad), 2 heads, 4 ii each
            const int t  = tid - 128;
            const int jj = t >> 2;
            const int q4 = t & 3;
            const size_t bj = (size_t)b*NN + j0 + jj;
            const float* kvr = g_kv + bj*448;
            const float* kqp = g_ksq + bj*8;
#pragma unroll
            for (int hh = 0; hh < 2; ++hh) {
                const int h = q4 + hh*4;
                float4 kf0 = *(const float4*)(kvr + h*16);
                float4 kf1 = *(const float4*)(kvr + h*16 + 4);
                float4 kf2 = *(const float4*)(kvr + h*16 + 8);
                float4 kf3 = *(const float4*)(kvr + h*16 + 12);
                float4 kp0 = *(const float4*)(kvr + 256 + h*12);
                float4 kp1 = *(const float4*)(kvr + 256 + h*12 + 4);
                float4 kp2 = *(const float4*)(kvr + 256 + h*12 + 8);
                float kq = kqp[h];
                float bz = bp_s[h];
                float cf = cf_s[h];
#pragma unroll
                for (int ii = 0; ii < IT; ++ii) {
                    const float* qsr = qs_s + ii*128 + h*16;
                    const float* qpr = qp_s + ii*96 + h*12;
                    float4 q0 = *(const float4*)(qsr);
                    float4 q1 = *(const float4*)(qsr + 4);
                    float4 q2 = *(const float4*)(qsr + 8);
                    float4 q3 = *(const float4*)(qsr + 12);
                    float s = q0.x*kf0.x + q0.y*kf0.y + q0.z*kf0.z + q0.w*kf0.w
                            + q1.x*kf1.x + q1.y*kf1.y + q1.z*kf1.z + q1.w*kf1.w
                            + q2.x*kf2.x + q2.y*kf2.y + q2.z*kf2.z + q2.w*kf2.w
                            + q3.x*kf3.x + q3.y*kf3.y + q3.z*kf3.z + q3.w*kf3.w;
                    float4 p0 = *(const float4*)(qpr);
                    float4 p1 = *(const float4*)(qpr + 4);
                    float4 p2 = *(const float4*)(qpr + 8);
                    float dt = p0.x*kp0.x + p0.y*kp0.y + p0.z*kp0.z + p0.w*kp0.w
                             + p1.x*kp1.x + p1.y*kp1.y + p1.z*kp1.z + p1.w*kp1.w
                             + p2.x*kp2.x + p2.y*kp2.y + p2.z*kp2.z + p2.w*kp2.w;
                    float dist = qsq_s[ii*8 + h] + kq - 2.f*dt;
                    wexp[ii*256 + h*32 + jj] = s*SCALAR_SCALE + bz + cf*dist;
                }
            }
        }
        __syncthreads();

        // ---- phase B: add bias into logits ----
#pragma unroll
        for (int l = 0; l < 4; ++l) {
            int idx = l*256 + tid;               // = ii*256 + h*32 + jj
            int ii = idx >> 8, h = (idx >> 5) & 7, jj = idx & 31;
            wexp[idx] += pbias[(ii*JT + jj)*8 + h];
        }
        __syncthreads();

        // ---- phase C: online softmax, warp w = head w, 4 ii ----
        {
#pragma unroll
            for (int ii = 0; ii < IT; ++ii) {
                float v = wexp[ii*256 + w*32 + lane];
                float mx = v;
#pragma unroll
                for (int off = 16; off; off >>= 1)
                    mx = fmaxf(mx, __shfl_xor_sync(0xffffffffu, mx, off));
                float mold = m_s[ii*8 + w];
                float mnew = fmaxf(mold, mx);
                float a = __expf(mold - mnew);
                float e = __expf(v - mnew);
                wexp[ii*256 + w*32 + lane] = e;
                float smv = e;
#pragma unroll
                for (int off = 16; off; off >>= 1)
                    smv += __shfl_xor_sync(0xffffffffu, smv, off);
                if (lane == 0) {
                    l_s[ii*8 + w] = l_s[ii*8 + w]*a + smv;
                    m_s[ii*8 + w] = mnew;
                    al_s[ii*8 + w] = a;
                }
            }
        }
        __syncthreads();

        // ---- phase D ----
        if (tid < 128) {
            // res_pair: warp w owns heads 2w,2w+1; lane owns p-quad
            const int h0 = 2*w, h1 = 2*w + 1;
#pragma unroll
            for (int ii = 0; ii < IT; ++ii) {
                float s0 = al_s[ii*8 + h0], s1 = al_s[ii*8 + h1];
                float4 A0 = a0[ii], A1 = a1[ii];
                A0.x *= s0; A0.y *= s0; A0.z *= s0; A0.w *= s0;
                A1.x *= s1; A1.y *= s1; A1.z *= s1; A1.w *= s1;
                const float* we0 = &wexp[ii*256 + h0*32];
                const float* we1 = &wexp[ii*256 + h1*32];
                const float* rowp = &pairT[(ii*JT)*132 + lane*4];
#pragma unroll
                for (int jj = 0; jj < JT; jj += 4) {
                    float4 wA = *(const float4*)(we0 + jj);
                    float4 wB = *(const float4*)(we1 + jj);
                    float4 r0 = *(const float4*)(rowp + (jj+0)*132);
                    float4 r1 = *(const float4*)(rowp + (jj+1)*132);
                    float4 r2 = *(const float4*)(rowp + (jj+2)*132);
                    float4 r3 = *(const float4*)(rowp + (jj+3)*132);
                    A0.x += wA.x*r0.x + wA.y*r1.x + wA.z*r2.x + wA.w*r3.x;
                    A0.y += wA.x*r0.y + wA.y*r1.y + wA.z*r2.y + wA.w*r3.y;
                    A0.z += wA.x*r0.z + wA.y*r1.z + wA.z*r2.z + wA.w*r3.z;
                    A0.w += wA.x*r0.w + wA.y*r1.w + wA.z*r2.w + wA.w*r3.w;
                    A1.x += wB.x*r0.x + wB.y*r1.x + wB.z*r2.x + wB.w*r3.x;
                    A1.y += wB.x*r0.y + wB.y*r1.y + wB.z*r2.y + wB.w*r3.y;
                    A1.z += wB.x*r0.z + wB.y*r1.z + wB.z*r2.z + wB.w*r3.z;
                    A1.w += wB.x*r0.w + wB.y*r1.w + wB.z*r2.w + wB.w*r3.w;
                }
                a0[ii] = A0; a1[ii] = A1;
            }
        } else {
            // values: scalar feats (all 128) + point feats (first 96)
#pragma unroll
            for (int ii = 0; ii < IT; ++ii) {
                accs[ii] *= al_s[ii*8 + hs];
                if (vp_act) accp[ii] *= al_s[ii*8 + hp];
            }
            const float* vbase = g_kv + ((size_t)b*NN + j0)*448;
            const float* svs = vbase + 128 + hs*16 + fs;
            const float* svp = vbase + 352 + hp*12 + fp;
#pragma unroll
            for (int jj4 = 0; jj4 < JT; jj4 += 4) {
                float v0 = svs[(size_t)(jj4+0)*448];
                float v1 = svs[(size_t)(jj4+1)*448];
                float v2 = svs[(size_t)(jj4+2)*448];
                float v3 = svs[(size_t)(jj4+3)*448];
#pragma unroll
                for (int ii = 0; ii < IT; ++ii) {
                    float4 w4 = *(const float4*)&wexp[ii*256 + hs*32 + jj4];
                    accs[ii] += w4.x*v0 + w4.y*v1 + w4.z*v2 + w4.w*v3;
                }
                if (vp_act) {
                    float u0 = svp[(size_t)(jj4+0)*448];
                    float u1 = svp[(size_t)(jj4+1)*448];
                    float u2 = svp[(size_t)(jj4+2)*448];
                    float u3 = svp[(size_t)(jj4+3)*448];
#pragma unroll
                    for (int ii = 0; ii < IT; ++ii) {
                        float4 w4 = *(const float4*)&wexp[ii*256 + hp*32 + jj4];
                        accp[ii] += w4.x*u0 + w4.y*u1 + w4.z*u2 + w4.w*u3;
                    }
                }
            }
        }
        __syncthreads();
    }

    // ---- finalize ----
    if (tid < 128) {
        const int h0 = 2*w, h1 = 2*w + 1;
#pragma unroll
        for (int ii = 0; ii < IT; ++ii) {
            float* fr = g_feats + (size_t)(b*NN + i0 + ii)*1280;
            float il0 = 1.0f / l_s[ii*8 + h0];
            float il1 = 1.0f / l_s[ii*8 + h1];
            float* d0 = fr + 256 + h0*128 + lane*4;
            d0[0] = a0[ii].x*il0; d0[1] = a0[ii].y*il0;
            d0[2] = a0[ii].z*il0; d0[3] = a0[ii].w*il0;
            float* d1 = fr + 256 + h1*128 + lane*4;
            d1[0] = a1[ii].x*il1; d1[1] = a1[ii].y*il1;
            d1[2] = a1[ii].z*il1; d1[3] = a1[ii].w*il1;
        }
    } else {
#pragma unroll
        for (int ii = 0; ii < IT; ++ii) {
            float* fr = g_feats + (size_t)(b*NN + i0 + ii)*1280;
            fr[hs*16 + fs] = accs[ii] / l_s[ii*8 + hs];
            if (vp_act) pts_s[ii*96 + hp*12 + fp] = accp[ii] / l_s[ii*8 + hp];
        }
    }
    __syncthreads();
    if (tid < 96) {
        int hd = tid / 3, r = tid - hd*3;
#pragma unroll
        for (int ii = 0; ii < IT; ++ii) {
            float c0 = pts_s[ii*96 + hd*3 + 0] - T_s[ii*3 + 0];
            float c1 = pts_s[ii*96 + hd*3 + 1] - T_s[ii*3 + 1];
            float c2 = pts_s[ii*96 + hd*3 + 2] - T_s[ii*3 + 2];
            float loc = c0*R_s[ii*9 + r*3 + 0] + c1*R_s[ii*9 + r*3 + 1] + c2*R_s[ii*9 + r*3 + 2];
            g_feats[(size_t)(b*NN + i0 + ii)*1280 + 128 + tid] = loc;
            ptl_s[ii*96 + tid] = loc;
        }
    }
    __syncthreads();
    if (tid < 128) {
        int ii = tid >> 5, hd = tid & 31;
        float x = ptl_s[ii*96 + hd*3], y = ptl_s[ii*96 + hd*3 + 1], z = ptl_s[ii*96 + hd*3 + 2];
        g_feats[(size_t)(b*NN + i0 + ii)*1280 + 224 + hd] = sqrtf(x*x + y*y + z*z + EPSV);
    }
}

// ---------------- launcher ----------------
extern "C" void kernel_launch(void* const* d_in, const int* in_sizes, int n_in,
                              void* d_out, int out_size)
{
    const float* q_single  = (const float*)d_in[0];
    const float* kv_single = (const float*)d_in[1];
    const float* pairwise  = (const float*)d_in[2];
    const float* rot       = (const float*)d_in[3];
    const float* trans     = (const float*)d_in[4];
    // d_in[5], d_in[6]: q_mask / kv_mask (all true) - unused
    const float* w_sq   = (const float*)d_in[7];
    const float* w_sk   = (const float*)d_in[8];
    const float* w_sv   = (const float*)d_in[9];
    const float* w_pq   = (const float*)d_in[10];
    const float* w_pk   = (const float*)d_in[11];
    const float* w_pv   = (const float*)d_in[12];
    const float* w_pair = (const float*)d_in[13];
    const float* b_pair = (const float*)d_in[14];
    const float* pw     = (const float*)d_in[15];
    const float* w_out  = (const float*)d_in[16];
    const float* b_out  = (const float*)d_in[17];
    float* out = (float*)d_out;

    float *p_q, *p_kv, *p_feats, *p_part;
    cudaGetSymbolAddress((void**)&p_q,  g_q);
    cudaGetSymbolAddress((void**)&p_kv, g_kv);
    cudaGetSymbolAddress((void**)&p_feats, g_feats);
    cudaGetSymbolAddress((void**)&p_part, g_part);

    static int smem_set = 0;
    if (!smem_set) {
        cudaFuncSetAttribute(ipa_attn_kernel,
                             cudaFuncAttributeMaxDynamicSharedMemorySize, SM_BYTES);
        smem_set = 1;
    }

    // all projections, one launch: 672 output cols -> grid (21, 16)
    proj_fused_kernel<<<dim3(21, 16), 256>>>(
        q_single, kv_single, w_sq, w_pq, w_sk, w_sv, w_pk, w_pv, p_q, p_kv);

    rotate_kernel<<<TOK, 32>>>(rot, trans);

    ipa_attn_kernel<<<BB*(NN/IT), 256, SM_BYTES>>>(pairwise, rot, trans, w_pair, b_pair, pw);

    // output projection, K split in 4: feats(1024x1280) @ w_out(1280x384)
    out_gemm_part<<<dim3(12, 16, 4), 256>>>(p_feats, w_out, p_part);
    add_bias_kernel<<<TOK*DIMV/256, 256>>>(b_out, out);
}

// round 6
// speedup vs baseline: 2.4304x; 1.0602x over previous
#include <cuda_runtime.h>
#include <math.h>
#include <stdint.h>

// Problem constants (fixed shapes)
#define BB   2
#define NN   512
#define DIMV 384
#define TOK  (BB*NN)          // 1024

#define SCALAR_SCALE 0.14433756729740643f   // (3*16)^-0.5
#define POINT_SCALE  0.13608276348795434f   // (3*4*4.5)^-0.5
#define PAIR_SCALE   0.57735026918962576f   // 3^-0.5
#define EPSV 1e-8f

// attention tiling
#define IT 4      // queries per block
#define JT 32     // keys per tile

// ---------------- device scratch ----------------
// g_q  row layout (stride 224): qs[0:128), qp[128:224)
// g_kv row layout (stride 448): ks[0:128), vs[128:256), kp[256:352), vp[352:448)
__device__ float g_q[TOK*224];
__device__ float g_kv[TOK*448];
__device__ float g_qsq[TOK*8];
__device__ float g_ksq[TOK*8];
__device__ float g_feats[TOK*1280];
__device__ float g_part[4*TOK*DIMV];

// =====================================================================
// Fused projection GEMM: all 6 projections in one launch.
// =====================================================================
__global__ __launch_bounds__(256) void proj_fused_kernel(
    const float* __restrict__ q_in, const float* __restrict__ kv_in,
    const float* __restrict__ w_sq, const float* __restrict__ w_pq,
    const float* __restrict__ w_sk, const float* __restrict__ w_sv,
    const float* __restrict__ w_pk, const float* __restrict__ w_pv,
    float* __restrict__ Cq, float* __restrict__ Ckv)
{
    __shared__ __align__(16) float As[16][68];
    __shared__ __align__(16) float Ws[16][32];

    const int tid  = threadIdx.x;
    const int row0 = blockIdx.y * 64;
    const int col0 = blockIdx.x * 32;

    const float* A; const float* W; int nseg, wcol;
    float* C; int Ctot, ccol;
    if (col0 < 128)      { A=q_in;  W=w_sq; nseg=128; wcol=col0;     C=Cq;  Ctot=224; ccol=col0; }
    else if (col0 < 224) { A=q_in;  W=w_pq; nseg=96;  wcol=col0-128; C=Cq;  Ctot=224; ccol=col0; }
    else if (col0 < 352) { A=kv_in; W=w_sk; nseg=128; wcol=col0-224; C=Ckv; Ctot=448; ccol=col0-224; }
    else if (col0 < 480) { A=kv_in; W=w_sv; nseg=128; wcol=col0-352; C=Ckv; Ctot=448; ccol=col0-224; }
    else if (col0 < 576) { A=kv_in; W=w_pk; nseg=96;  wcol=col0-480; C=Ckv; Ctot=448; ccol=col0-224; }
    else                 { A=kv_in; W=w_pv; nseg=96;  wcol=col0-576; C=Ckv; Ctot=448; ccol=col0-224; }

    const int my = tid >> 4;
    const int nx = tid & 15;

    float acc[4][2];
#pragma unroll
    for (int i = 0; i < 4; ++i) { acc[i][0] = 0.f; acc[i][1] = 0.f; }

    const int lr = tid >> 2;
    const int lk = (tid & 3) * 4;

    for (int k0 = 0; k0 < DIMV; k0 += 16) {
        float4 av = *(const float4*)(A + (size_t)(row0 + lr)*DIMV + k0 + lk);
        As[lk+0][lr] = av.x; As[lk+1][lr] = av.y;
        As[lk+2][lr] = av.z; As[lk+3][lr] = av.w;
        if (tid < 128) {
            int wk = tid >> 3, wn = (tid & 7) * 4;
            *(float4*)&Ws[wk][wn] = *(const float4*)(W + (size_t)(k0 + wk)*nseg + wcol + wn);
        }
        __syncthreads();
#pragma unroll
        for (int kk = 0; kk < 16; ++kk) {
            float4 a = *(const float4*)&As[kk][my*4];
            float2 w = *(const float2*)&Ws[kk][nx*2];
            acc[0][0] += a.x*w.x; acc[0][1] += a.x*w.y;
            acc[1][0] += a.y*w.x; acc[1][1] += a.y*w.y;
            acc[2][0] += a.z*w.x; acc[2][1] += a.z*w.y;
            acc[3][0] += a.w*w.x; acc[3][1] += a.w*w.y;
        }
        __syncthreads();
    }
#pragma unroll
    for (int i = 0; i < 4; ++i) {
        float* cr = C + (size_t)(row0 + my*4 + i)*Ctot + ccol + nx*2;
        cr[0] = acc[i][0]; cr[1] = acc[i][1];
    }
}

// =====================================================================
// Output GEMM, 64x64 tile, 4x4 per thread, K split in 4 via blockIdx.z.
// grid (6, 16, 4)
// =====================================================================
__global__ __launch_bounds__(256) void out_gemm_part(
    const float* __restrict__ A, const float* __restrict__ W,
    float* __restrict__ P)
{
    __shared__ __align__(16) float As[16][68];
    __shared__ __align__(16) float Ws[16][68];

    const int tid  = threadIdx.x;
    const int row0 = blockIdx.y * 64;
    const int col0 = blockIdx.x * 64;
    const int kh   = blockIdx.z;
    const int my = tid >> 4;          // 0..15 -> rows my*4..+3
    const int nx = tid & 15;          // 0..15 -> cols nx*4..+3

    float acc[4][4];
#pragma unroll
    for (int i = 0; i < 4; ++i)
#pragma unroll
        for (int j = 0; j < 4; ++j) acc[i][j] = 0.f;

    const int lr = tid >> 2;          // A loader row 0..63
    const int lk = (tid & 3) * 4;     // A loader k
    const int wk = tid >> 4;          // W loader k 0..15
    const int wn = (tid & 15) * 4;    // W loader col

    const int kbeg = kh * 320, kend = kbeg + 320;

    for (int k0 = kbeg; k0 < kend; k0 += 16) {
        float4 av = *(const float4*)(A + (size_t)(row0 + lr)*1280 + k0 + lk);
        As[lk+0][lr] = av.x; As[lk+1][lr] = av.y;
        As[lk+2][lr] = av.z; As[lk+3][lr] = av.w;
        *(float4*)&Ws[wk][wn] = *(const float4*)(W + (size_t)(k0 + wk)*DIMV + col0 + wn);
        __syncthreads();
#pragma unroll
        for (int kk = 0; kk < 16; ++kk) {
            float4 a = *(const float4*)&As[kk][my*4];
            float4 w = *(const float4*)&Ws[kk][nx*4];
            acc[0][0] += a.x*w.x; acc[0][1] += a.x*w.y; acc[0][2] += a.x*w.z; acc[0][3] += a.x*w.w;
            acc[1][0] += a.y*w.x; acc[1][1] += a.y*w.y; acc[1][2] += a.y*w.z; acc[1][3] += a.y*w.w;
            acc[2][0] += a.z*w.x; acc[2][1] += a.z*w.y; acc[2][2] += a.z*w.z; acc[2][3] += a.z*w.w;
            acc[3][0] += a.w*w.x; acc[3][1] += a.w*w.y; acc[3][2] += a.w*w.z; acc[3][3] += a.w*w.w;
        }
        __syncthreads();
    }
    float* dst = P + (size_t)kh*TOK*DIMV;
#pragma unroll
    for (int i = 0; i < 4; ++i) {
        float* cr = dst + (size_t)(row0 + my*4 + i)*DIMV + col0 + nx*4;
        cr[0] = acc[i][0]; cr[1] = acc[i][1]; cr[2] = acc[i][2]; cr[3] = acc[i][3];
    }
}

__global__ __launch_bounds__(256) void add_bias_kernel(
    const float* __restrict__ bias, float* __restrict__ out)
{
    int idx = blockIdx.x * 256 + threadIdx.x;   // 1024*384 total
    const int S = TOK*DIMV;
    out[idx] = g_part[idx] + g_part[S + idx] + g_part[2*S + idx]
             + g_part[3*S + idx] + bias[idx % DIMV];
}

// ---------------- rotate + translate qp/kp/vp in place, squared norms ----
__global__ void rotate_kernel(const float* __restrict__ rot,
                              const float* __restrict__ trans)
{
    const int bn  = blockIdx.x;
    const int tid = threadIdx.x;   // 0..31: h = tid/4, d = tid%4

    float r[9], t3[3];
#pragma unroll
    for (int k = 0; k < 9; ++k) r[k] = rot[bn*9 + k];
#pragma unroll
    for (int k = 0; k < 3; ++k) t3[k] = trans[bn*3 + k];

    float* arrs[3] = { g_q  + (size_t)bn*224 + 128,
                       g_kv + (size_t)bn*448 + 256,
                       g_kv + (size_t)bn*448 + 352 };
    float sq0 = 0.f, sq1 = 0.f;
#pragma unroll
    for (int a = 0; a < 3; ++a) {
        float* base = arrs[a] + tid*3;
        float c0 = base[0], c1 = base[1], c2 = base[2];
        float o0 = c0*r[0] + c1*r[3] + c2*r[6] + t3[0];
        float o1 = c0*r[1] + c1*r[4] + c2*r[7] + t3[1];
        float o2 = c0*r[2] + c1*r[5] + c2*r[8] + t3[2];
        base[0] = o0; base[1] = o1; base[2] = o2;
        float s = o0*o0 + o1*o1 + o2*o2;
        if (a == 0) sq0 = s;
        if (a == 1) sq1 = s;
    }
#pragma unroll
    for (int off = 1; off < 4; off <<= 1) {
        sq0 += __shfl_xor_sync(0xffffffffu, sq0, off);
        sq1 += __shfl_xor_sync(0xffffffffu, sq1, off);
    }
    if ((tid & 3) == 0) {
        g_qsq[bn*8 + (tid >> 2)] = sq0;
        g_ksq[bn*8 + (tid >> 2)] = sq1;
    }
}

// =====================================================================
// Fused attention: 4 queries per block, j-tile 32, dynamic smem.
// Pair tile stored XOR-swizzled: logical quad q of row at q ^ (row&7).
// grid = 256 (BB * NN/4), 256 threads.
// =====================================================================
// smem float offsets
#define OF_PAIR  0                      // 128 rows x 128 (swizzled)
#define OF_WEXP  16384                  // [ii][h][jj] 4*8*32
#define OF_PBIAS 17408                  // [h][row]    8*128 (transposed)
#define OF_WPM   18432                  // [p][h]      128*8 (pre-scaled)
#define OF_QS    19456                  // [ii][128]
#define OF_QP    19968                  // [ii][96]
#define OF_QSQ   20352                  // [ii][8]
#define OF_M     20384                  // [ii][8]
#define OF_L     20416
#define OF_ALPHA 20448
#define OF_COEF  20480                  // [8]
#define OF_BP    20488                  // [8]
#define OF_R     20496                  // [ii][9]
#define OF_T     20532                  // [ii][3]
#define OF_PTS   20544                  // [ii][96]
#define OF_PTSL  20928                  // [ii][96]
#define SM_FLOATS 21312
#define SM_BYTES (SM_FLOATS*4)

__global__ __launch_bounds__(256) void ipa_attn_kernel(
    const float* __restrict__ pairwise,
    const float* __restrict__ rot,
    const float* __restrict__ trans,
    const float* __restrict__ w_pair,
    const float* __restrict__ b_pair,
    const float* __restrict__ point_w)
{
    extern __shared__ __align__(16) float sm[];
    float* pairT = sm + OF_PAIR;
    float* wexp  = sm + OF_WEXP;
    float* pbias = sm + OF_PBIAS;
    float* wpm   = sm + OF_WPM;
    float* qs_s  = sm + OF_QS;
    float* qp_s  = sm + OF_QP;
    float* qsq_s = sm + OF_QSQ;
    float* m_s   = sm + OF_M;
    float* l_s   = sm + OF_L;
    float* al_s  = sm + OF_ALPHA;
    float* cf_s  = sm + OF_COEF;
    float* bp_s  = sm + OF_BP;
    float* R_s   = sm + OF_R;
    float* T_s   = sm + OF_T;
    float* pts_s = sm + OF_PTS;
    float* ptl_s = sm + OF_PTSL;

    const int tid  = threadIdx.x;
    const int bid  = blockIdx.x;
    const int b    = bid >> 7;
    const int i0   = (bid & 127) * IT;
    const int w    = tid >> 5;
    const int lane = tid & 31;

    // ---- prologue loads ----
#pragma unroll
    for (int l = 0; l < 2; ++l) {             // qs: 512 floats
        int idx = l*256 + tid;
        int ii = idx >> 7;
        qs_s[idx] = g_q[(size_t)(b*NN + i0 + ii)*224 + (idx & 127)];
    }
#pragma unroll
    for (int idx = tid; idx < IT*96; idx += 256) {   // qp: 384 floats
        int ii = idx / 96;
        qp_s[idx] = g_q[(size_t)(b*NN + i0 + ii)*224 + 128 + (idx % 96)];
    }
    if (tid < 32) {
        int ii = tid >> 3;
        qsq_s[tid] = g_qsq[(size_t)(b*NN + i0 + ii)*8 + (tid & 7)];
        m_s[tid] = -1e30f;
        l_s[tid] = 0.f;
    }
    if (tid < 8) {
        bp_s[tid] = b_pair[tid] * PAIR_SCALE;
        float x = point_w[tid];
        cf_s[tid] = -0.5f * POINT_SCALE * log1pf(__expf(x));
    }
#pragma unroll
    for (int l = 0; l < 4; ++l) wpm[l*256 + tid] = w_pair[l*256 + tid] * PAIR_SCALE;
    if (tid >= 64 && tid < 100) {             // R: 36
        int idx = tid - 64;
        int ii = idx / 9;
        R_s[idx] = rot[(size_t)(b*NN + i0 + ii)*9 + (idx % 9)];
    }
    if (tid >= 100 && tid < 112) {            // T: 12
        int idx = tid - 100;
        int ii = idx / 3;
        T_s[idx] = trans[(size_t)(b*NN + i0 + ii)*3 + (idx % 3)];
    }
    __syncthreads();

    // persistent accumulators
    float4 a0[IT], a1[IT];                    // res_pair (warps 0-3): heads 2w,2w+1
#pragma unroll
    for (int ii = 0; ii < IT; ++ii) { a0[ii] = make_float4(0,0,0,0); a1[ii] = make_float4(0,0,0,0); }
    float accs[IT] = {0,0,0,0}, accp[IT] = {0,0,0,0};   // value (warps 4-7)
    const int tv = tid - 128;                 // 0..127 for warps 4-7
    const int hs = (tv >= 0) ? (tv >> 4) : 0;
    const int fs = (tv >= 0) ? (tv & 15) : 0;
    const bool vp_act = (tv >= 0) && (tv < 96);
    const int hp = vp_act ? (tv / 12) : 0;
    const int fp = vp_act ? (tv % 12) : 0;

    const float* gp_base = pairwise + ((size_t)b*NN + i0) * NN * 128;
    const int lane4 = lane << 2;

    for (int tile = 0; tile < 16; ++tile) {
        const int j0 = tile * JT;
        // ---- load pair tiles: 4 ii x 32 jj x 128 p (XOR swizzled quads) ----
        {
#pragma unroll
            for (int l = 0; l < 16; ++l) {
                int idx = l*256 + tid;              // float4 index, 4096 total
                int ii  = idx >> 10;
                int rem = idx & 1023;
                int jj  = rem >> 5;
                int q   = rem & 31;
                int physq = q ^ (jj & 7);           // row&7 == jj&7
                *(float4*)&pairT[((ii*JT + jj) << 7) + (physq << 2)] =
                    *(const float4*)(gp_base + ((size_t)ii*NN + j0 + jj)*128 + (q << 2));
            }
        }
        __syncthreads();

        // ---- phase A ----
        if (tid < 128) {
            // bias: row = (ii,jj), all 8 heads, full p; swizzled conflict-free reads
            const int row = tid;
            const float* prow = &pairT[row << 7];
            const int rk = row & 7;
            float acc[8];
#pragma unroll
            for (int h = 0; h < 8; ++h) acc[h] = 0.f;
#pragma unroll 8
            for (int i = 0; i < 32; ++i) {
                float4 pv = *(const float4*)(prow + ((i ^ rk) << 2));
                const float* wp = &wpm[i*32];       // p = i*4.., uniform (broadcast)
                float pe[4] = { pv.x, pv.y, pv.z, pv.w };
#pragma unroll
                for (int e = 0; e < 4; ++e) {
                    float4 wa = *(const float4*)(wp + e*8);
                    float4 wb = *(const float4*)(wp + e*8 + 4);
                    acc[0] += pe[e]*wa.x; acc[1] += pe[e]*wa.y;
                    acc[2] += pe[e]*wa.z; acc[3] += pe[e]*wa.w;
                    acc[4] += pe[e]*wb.x; acc[5] += pe[e]*wb.y;
                    acc[6] += pe[e]*wb.z; acc[7] += pe[e]*wb.w;
                }
            }
#pragma unroll
            for (int h = 0; h < 8; ++h) pbias[h*128 + row] = acc[h];
        } else {
            // z-base: t -> (jj, head-quad), 2 heads, 4 ii each
            const int t  = tid - 128;
            const int jj = t >> 2;
            const int q4 = t & 3;
            const size_t bj = (size_t)b*NN + j0 + jj;
            const float* kvr = g_kv + bj*448;
            const float* kqp = g_ksq + bj*8;
#pragma unroll
            for (int hh = 0; hh < 2; ++hh) {
                const int h = q4 + hh*4;
                float4 kf0 = *(const float4*)(kvr + h*16);
                float4 kf1 = *(const float4*)(kvr + h*16 + 4);
                float4 kf2 = *(const float4*)(kvr + h*16 + 8);
                float4 kf3 = *(const float4*)(kvr + h*16 + 12);
                float4 kp0 = *(const float4*)(kvr + 256 + h*12);
                float4 kp1 = *(const float4*)(kvr + 256 + h*12 + 4);
                float4 kp2 = *(const float4*)(kvr + 256 + h*12 + 8);
                float kq = kqp[h];
                float bz = bp_s[h];
                float cf = cf_s[h];
#pragma unroll
                for (int ii = 0; ii < IT; ++ii) {
                    const float* qsr = qs_s + ii*128 + h*16;
                    const float* qpr = qp_s + ii*96 + h*12;
                    float4 q0 = *(const float4*)(qsr);
                    float4 q1 = *(const float4*)(qsr + 4);
                    float4 q2 = *(const float4*)(qsr + 8);
                    float4 q3 = *(const float4*)(qsr + 12);
                    float s = q0.x*kf0.x + q0.y*kf0.y + q0.z*kf0.z + q0.w*kf0.w
                            + q1.x*kf1.x + q1.y*kf1.y + q1.z*kf1.z + q1.w*kf1.w
                            + q2.x*kf2.x + q2.y*kf2.y + q2.z*kf2.z + q2.w*kf2.w
                            + q3.x*kf3.x + q3.y*kf3.y + q3.z*kf3.z + q3.w*kf3.w;
                    float4 p0 = *(const float4*)(qpr);
                    float4 p1 = *(const float4*)(qpr + 4);
                    float4 p2 = *(const float4*)(qpr + 8);
                    float dt = p0.x*kp0.x + p0.y*kp0.y + p0.z*kp0.z + p0.w*kp0.w
                             + p1.x*kp1.x + p1.y*kp1.y + p1.z*kp1.z + p1.w*kp1.w
                             + p2.x*kp2.x + p2.y*kp2.y + p2.z*kp2.z + p2.w*kp2.w;
                    float dist = qsq_s[ii*8 + h] + kq - 2.f*dt;
                    wexp[ii*256 + h*32 + jj] = s*SCALAR_SCALE + bz + cf*dist;
                }
            }
        }
        __syncthreads();

        // ---- phase B: add bias into logits (pbias is [h][row]) ----
#pragma unroll
        for (int l = 0; l < 4; ++l) {
            int idx = l*256 + tid;               // = ii*256 + h*32 + jj
            int ii = idx >> 8, h = (idx >> 5) & 7, jj = idx & 31;
            wexp[idx] += pbias[h*128 + ii*JT + jj];
        }
        __syncthreads();

        // ---- phase C: online softmax, warp w = head w, 4 ii ----
        {
#pragma unroll
            for (int ii = 0; ii < IT; ++ii) {
                float v = wexp[ii*256 + w*32 + lane];
                float mx = v;
#pragma unroll
                for (int off = 16; off; off >>= 1)
                    mx = fmaxf(mx, __shfl_xor_sync(0xffffffffu, mx, off));
                float mold = m_s[ii*8 + w];
                float mnew = fmaxf(mold, mx);
                float a = __expf(mold - mnew);
                float e = __expf(v - mnew);
                wexp[ii*256 + w*32 + lane] = e;
                float smv = e;
#pragma unroll
                for (int off = 16; off; off >>= 1)
                    smv += __shfl_xor_sync(0xffffffffu, smv, off);
                if (lane == 0) {
                    l_s[ii*8 + w] = l_s[ii*8 + w]*a + smv;
                    m_s[ii*8 + w] = mnew;
                    al_s[ii*8 + w] = a;
                }
            }
        }
        __syncthreads();

        // ---- phase D ----
        if (tid < 128) {
            // res_pair: warp w owns heads 2w,2w+1; lane owns logical p-quad = lane
            const int h0 = 2*w, h1 = 2*w + 1;
#pragma unroll
            for (int ii = 0; ii < IT; ++ii) {
                float s0 = al_s[ii*8 + h0], s1 = al_s[ii*8 + h1];
                float4 A0 = a0[ii], A1 = a1[ii];
                A0.x *= s0; A0.y *= s0; A0.z *= s0; A0.w *= s0;
                A1.x *= s1; A1.y *= s1; A1.z *= s1; A1.w *= s1;
                const float* we0 = &wexp[ii*256 + h0*32];
                const float* we1 = &wexp[ii*256 + h1*32];
                const float* tb  = &pairT[(ii*JT) << 7];
#pragma unroll
                for (int jj = 0; jj < JT; jj += 4) {
                    float4 wA = *(const float4*)(we0 + jj);
                    float4 wB = *(const float4*)(we1 + jj);
                    float4 r0 = *(const float4*)(tb + ((jj+0)<<7) + (lane4 ^ (((jj+0)&7)<<2)));
                    float4 r1 = *(const float4*)(tb + ((jj+1)<<7) + (lane4 ^ (((jj+1)&7)<<2)));
                    float4 r2 = *(const float4*)(tb + ((jj+2)<<7) + (lane4 ^ (((jj+2)&7)<<2)));
                    float4 r3 = *(const float4*)(tb + ((jj+3)<<7) + (lane4 ^ (((jj+3)&7)<<2)));
                    A0.x += wA.x*r0.x + wA.y*r1.x + wA.z*r2.x + wA.w*r3.x;
                    A0.y += wA.x*r0.y + wA.y*r1.y + wA.z*r2.y + wA.w*r3.y;
                    A0.z += wA.x*r0.z + wA.y*r1.z + wA.z*r2.z + wA.w*r3.z;
                    A0.w += wA.x*r0.w + wA.y*r1.w + wA.z*r2.w + wA.w*r3.w;
                    A1.x += wB.x*r0.x + wB.y*r1.x + wB.z*r2.x + wB.w*r3.x;
                    A1.y += wB.x*r0.y + wB.y*r1.y + wB.z*r2.y + wB.w*r3.y;
                    A1.z += wB.x*r0.z + wB.y*r1.z + wB.z*r2.z + wB.w*r3.z;
                    A1.w += wB.x*r0.w + wB.y*r1.w + wB.z*r2.w + wB.w*r3.w;
                }
                a0[ii] = A0; a1[ii] = A1;
            }
        } else {
            // values: scalar feats (all 128) + point feats (first 96)
#pragma unroll
            for (int ii = 0; ii < IT; ++ii) {
                accs[ii] *= al_s[ii*8 + hs];
                if (vp_act) accp[ii] *= al_s[ii*8 + hp];
            }
            const float* vbase = g_kv + ((size_t)b*NN + j0)*448;
            const float* svs = vbase + 128 + hs*16 + fs;
            const float* svp = vbase + 352 + hp*12 + fp;
#pragma unroll
            for (int jj4 = 0; jj4 < JT; jj4 += 4) {
                float v0 = svs[(size_t)(jj4+0)*448];
                float v1 = svs[(size_t)(jj4+1)*448];
                float v2 = svs[(size_t)(jj4+2)*448];
                float v3 = svs[(size_t)(jj4+3)*448];
#pragma unroll
                for (int ii = 0; ii < IT; ++ii) {
                    float4 w4 = *(const float4*)&wexp[ii*256 + hs*32 + jj4];
                    accs[ii] += w4.x*v0 + w4.y*v1 + w4.z*v2 + w4.w*v3;
                }
                if (vp_act) {
                    float u0 = svp[(size_t)(jj4+0)*448];
                    float u1 = svp[(size_t)(jj4+1)*448];
                    float u2 = svp[(size_t)(jj4+2)*448];
                    float u3 = svp[(size_t)(jj4+3)*448];
#pragma unroll
                    for (int ii = 0; ii < IT; ++ii) {
                        float4 w4 = *(const float4*)&wexp[ii*256 + hp*32 + jj4];
                        accp[ii] += w4.x*u0 + w4.y*u1 + w4.z*u2 + w4.w*u3;
                    }
                }
            }
        }
        __syncthreads();
    }

    // ---- finalize ----
    if (tid < 128) {
        const int h0 = 2*w, h1 = 2*w + 1;
#pragma unroll
        for (int ii = 0; ii < IT; ++ii) {
            float* fr = g_feats + (size_t)(b*NN + i0 + ii)*1280;
            float il0 = 1.0f / l_s[ii*8 + h0];
            float il1 = 1.0f / l_s[ii*8 + h1];
            float* d0 = fr + 256 + h0*128 + lane*4;
            d0[0] = a0[ii].x*il0; d0[1] = a0[ii].y*il0;
            d0[2] = a0[ii].z*il0; d0[3] = a0[ii].w*il0;
            float* d1 = fr + 256 + h1*128 + lane*4;
            d1[0] = a1[ii].x*il1; d1[1] = a1[ii].y*il1;
            d1[2] = a1[ii].z*il1; d1[3] = a1[ii].w*il1;
        }
    } else {
#pragma unroll
        for (int ii = 0; ii < IT; ++ii) {
            float* fr = g_feats + (size_t)(b*NN + i0 + ii)*1280;
            fr[hs*16 + fs] = accs[ii] / l_s[ii*8 + hs];
            if (vp_act) pts_s[ii*96 + hp*12 + fp] = accp[ii] / l_s[ii*8 + hp];
        }
    }
    __syncthreads();
    if (tid < 96) {
        int hd = tid / 3, r = tid - hd*3;
#pragma unroll
        for (int ii = 0; ii < IT; ++ii) {
            float c0 = pts_s[ii*96 + hd*3 + 0] - T_s[ii*3 + 0];
            float c1 = pts_s[ii*96 + hd*3 + 1] - T_s[ii*3 + 1];
            float c2 = pts_s[ii*96 + hd*3 + 2] - T_s[ii*3 + 2];
            float loc = c0*R_s[ii*9 + r*3 + 0] + c1*R_s[ii*9 + r*3 + 1] + c2*R_s[ii*9 + r*3 + 2];
            g_feats[(size_t)(b*NN + i0 + ii)*1280 + 128 + tid] = loc;
            ptl_s[ii*96 + tid] = loc;
        }
    }
    __syncthreads();
    if (tid < 128) {
        int ii = tid >> 5, hd = tid & 31;
        float x = ptl_s[ii*96 + hd*3], y = ptl_s[ii*96 + hd*3 + 1], z = ptl_s[ii*96 + hd*3 + 2];
        g_feats[(size_t)(b*NN + i0 + ii)*1280 + 224 + hd] = sqrtf(x*x + y*y + z*z + EPSV);
    }
}

// ---------------- launcher ----------------
extern "C" void kernel_launch(void* const* d_in, const int* in_sizes, int n_in,
                              void* d_out, int out_size)
{
    const float* q_single  = (const float*)d_in[0];
    const float* kv_single = (const float*)d_in[1];
    const float* pairwise  = (const float*)d_in[2];
    const float* rot       = (const float*)d_in[3];
    const float* trans     = (const float*)d_in[4];
    // d_in[5], d_in[6]: q_mask / kv_mask (all true) - unused
    const float* w_sq   = (const float*)d_in[7];
    const float* w_sk   = (const float*)d_in[8];
    const float* w_sv   = (const float*)d_in[9];
    const float* w_pq   = (const float*)d_in[10];
    const float* w_pk   = (const float*)d_in[11];
    const float* w_pv   = (const float*)d_in[12];
    const float* w_pair = (const float*)d_in[13];
    const float* b_pair = (const float*)d_in[14];
    const float* pw     = (const float*)d_in[15];
    const float* w_out  = (const float*)d_in[16];
    const float* b_out  = (const float*)d_in[17];
    float* out = (float*)d_out;

    float *p_q, *p_kv, *p_feats, *p_part;
    cudaGetSymbolAddress((void**)&p_q,  g_q);
    cudaGetSymbolAddress((void**)&p_kv, g_kv);
    cudaGetSymbolAddress((void**)&p_feats, g_feats);
    cudaGetSymbolAddress((void**)&p_part, g_part);

    static int smem_set = 0;
    if (!smem_set) {
        cudaFuncSetAttribute(ipa_attn_kernel,
                             cudaFuncAttributeMaxDynamicSharedMemorySize, SM_BYTES);
        smem_set = 1;
    }

    // all projections, one launch: 672 output cols -> grid (21, 16)
    proj_fused_kernel<<<dim3(21, 16), 256>>>(
        q_single, kv_single, w_sq, w_pq, w_sk, w_sv, w_pk, w_pv, p_q, p_kv);

    rotate_kernel<<<TOK, 32>>>(rot, trans);

    ipa_attn_kernel<<<BB*(NN/IT), 256, SM_BYTES>>>(pairwise, rot, trans, w_pair, b_pair, pw);

    // output projection, K split in 4: feats(1024x1280) @ w_out(1280x384)
    out_gemm_part<<<dim3(6, 16, 4), 256>>>(p_feats, w_out, p_part);
    add_bias_kernel<<<TOK*DIMV/256, 256>>>(b_out, out);
}